// round 1
// baseline (speedup 1.0000x reference)
#include <cuda_runtime.h>

#define N_NODES 50000
#define N_EDGES 800000
#define D 128
#define EPS 1e-5f

// Scratch (allocation-free rule: __device__ globals)
__device__ float g_agg[N_NODES * D];
__device__ float g_bufA[N_NODES * D];
__device__ float g_bufB[N_NODES * D];
__device__ float g_deg[N_NODES];
__device__ float g_invdeg[N_NODES];
__device__ float g_stats[2 * D];    // [0..127] = col sums, [128..255] = col sumsq
__device__ float g_affine[2 * D];   // [0..127] = scale,    [128..255] = shift

// ---------------------------------------------------------------------------
__global__ void zero_kernel(float4* __restrict__ p, int n4) {
    int i = blockIdx.x * blockDim.x + threadIdx.x;
    if (i < n4) p[i] = make_float4(0.f, 0.f, 0.f, 0.f);
}

__global__ void deg_kernel(const int* __restrict__ dst, float* __restrict__ deg) {
    int e = blockIdx.x * blockDim.x + threadIdx.x;
    if (e < N_EDGES) atomicAdd(&deg[dst[e]], 1.0f);
}

__global__ void invdeg_kernel(const float* __restrict__ deg, float* __restrict__ inv) {
    int i = blockIdx.x * blockDim.x + threadIdx.x;
    if (i < N_NODES) inv[i] = 1.0f / fmaxf(deg[i], 1.0f);
}

// One warp per edge: 32 lanes each move one float4 of the 512B feature row.
__global__ void scatter_kernel(const float* __restrict__ X,
                               const int* __restrict__ src,
                               const int* __restrict__ dst,
                               float* __restrict__ agg) {
    int gid = blockIdx.x * blockDim.x + threadIdx.x;
    int e = gid >> 5;
    if (e >= N_EDGES) return;
    int c = gid & 31;
    int s = __ldg(&src[e]);
    int d = __ldg(&dst[e]);
    float4 v = ((const float4*)X)[s * 32 + c];
    float4* p = ((float4*)agg) + (size_t)d * 32 + c;
    asm volatile("red.global.add.v4.f32 [%0], {%1, %2, %3, %4};"
                 :: "l"(p), "f"(v.x), "f"(v.y), "f"(v.z), "f"(v.w)
                 : "memory");
}

// ---------------------------------------------------------------------------
// Fused: Out = Xin @ Ws + (Agg * invdeg) @ Wn + bias, plus (optional) BN
// column partial sums/sumsq accumulated into g_stats.
// Block: 256 threads -> 64-row x 128-col output tile, 8x4 register tile/thread.
__global__ __launch_bounds__(256) void gemm_bn_kernel(
    const float* __restrict__ Xin,
    const float* __restrict__ Agg,
    const float* __restrict__ invdeg,
    const float* __restrict__ Ws,     // [k][j] 128x128
    const float* __restrict__ Wn,     // [k][j] 128x128
    const float* __restrict__ bias,   // [128]
    float* __restrict__ Out,
    float* __restrict__ stats,        // 256 floats (sums, sumsq)
    int withBN)
{
    __shared__ float Xs[64 * 128];    // 32 KB input tile
    __shared__ float s_sum[128];
    __shared__ float s_sumsq[128];

    const int tid = threadIdx.x;
    const int tx = tid & 31;          // column group: cols 4*tx .. 4*tx+3
    const int ty = tid >> 5;          // row group (== warp id): rows 8*ty .. 8*ty+7
    const int row0 = blockIdx.x * 64;

    float acc[8][4];
#pragma unroll
    for (int r = 0; r < 8; ++r)
#pragma unroll
        for (int c = 0; c < 4; ++c) acc[r][c] = 0.f;

#pragma unroll
    for (int pass = 0; pass < 2; ++pass) {
        const float* srcp = (pass == 0) ? Xin : Agg;
        const float4* W4 = (const float4*)((pass == 0) ? Ws : Wn);

        __syncthreads();  // protect Xs reads from previous pass
#pragma unroll
        for (int i = 0; i < 8; ++i) {
            int idx = tid + i * 256;          // 0..2047 float4 slots
            int r = idx >> 5;
            int c = idx & 31;
            int gr = row0 + r;
            float4 v = make_float4(0.f, 0.f, 0.f, 0.f);
            if (gr < N_NODES) {
                v = ((const float4*)srcp)[(size_t)gr * 32 + c];
                if (pass == 1) {
                    float f = __ldg(&invdeg[gr]);
                    v.x *= f; v.y *= f; v.z *= f; v.w *= f;
                }
            }
            ((float4*)Xs)[idx] = v;
        }
        __syncthreads();

#pragma unroll 4
        for (int k = 0; k < 128; ++k) {
            float4 w = __ldg(&W4[k * 32 + tx]);
#pragma unroll
            for (int r = 0; r < 8; ++r) {
                float xv = Xs[(ty * 8 + r) * 128 + k];
                acc[r][0] = fmaf(xv, w.x, acc[r][0]);
                acc[r][1] = fmaf(xv, w.y, acc[r][1]);
                acc[r][2] = fmaf(xv, w.z, acc[r][2]);
                acc[r][3] = fmaf(xv, w.w, acc[r][3]);
            }
        }
    }

    if (withBN) {
        if (tid < 128) { s_sum[tid] = 0.f; s_sumsq[tid] = 0.f; }
    }
    __syncthreads();

    float4 b4 = __ldg(&((const float4*)bias)[tx]);
    float ps[4] = {0.f, 0.f, 0.f, 0.f};
    float ps2[4] = {0.f, 0.f, 0.f, 0.f};

#pragma unroll
    for (int r = 0; r < 8; ++r) {
        int gr = row0 + ty * 8 + r;
        if (gr < N_NODES) {
            float4 h;
            h.x = acc[r][0] + b4.x;
            h.y = acc[r][1] + b4.y;
            h.z = acc[r][2] + b4.z;
            h.w = acc[r][3] + b4.w;
            ((float4*)Out)[(size_t)gr * 32 + tx] = h;
            if (withBN) {
                ps[0] += h.x; ps2[0] += h.x * h.x;
                ps[1] += h.y; ps2[1] += h.y * h.y;
                ps[2] += h.z; ps2[2] += h.z * h.z;
                ps[3] += h.w; ps2[3] += h.w * h.w;
            }
        }
    }

    if (withBN) {
#pragma unroll
        for (int c = 0; c < 4; ++c) {
            atomicAdd(&s_sum[tx * 4 + c], ps[c]);
            atomicAdd(&s_sumsq[tx * 4 + c], ps2[c]);
        }
        __syncthreads();
        if (tid < 128) {
            atomicAdd(&stats[tid], s_sum[tid]);
            atomicAdd(&stats[128 + tid], s_sumsq[tid]);
        }
    }
}

// ---------------------------------------------------------------------------
__global__ void bn_finalize_kernel(const float* __restrict__ stats,
                                   const float* __restrict__ gamma,
                                   const float* __restrict__ beta,
                                   float* __restrict__ affine) {
    int j = threadIdx.x;  // 128 threads
    const float invN = 1.0f / (float)N_NODES;
    float mu = stats[j] * invN;
    float var = stats[128 + j] * invN - mu * mu;
    float sc = gamma[j] * rsqrtf(var + EPS);
    affine[j] = sc;
    affine[128 + j] = beta[j] - mu * sc;
}

__global__ void bn_apply_kernel(float4* __restrict__ buf,
                                const float* __restrict__ affine) {
    int gid = blockIdx.x * blockDim.x + threadIdx.x;
    if (gid >= N_NODES * 32) return;
    int c = gid & 31;
    const float4* sc4 = (const float4*)affine;
    const float4* sh4 = (const float4*)(affine + 128);
    float4 sc = __ldg(&sc4[c]);
    float4 sh = __ldg(&sh4[c]);
    float4 v = buf[gid];
    v.x = fmaxf(fmaf(v.x, sc.x, sh.x), 0.f);
    v.y = fmaxf(fmaf(v.y, sc.y, sh.y), 0.f);
    v.z = fmaxf(fmaf(v.z, sc.z, sh.z), 0.f);
    v.w = fmaxf(fmaf(v.w, sc.w, sh.w), 0.f);
    buf[gid] = v;
}

// ---------------------------------------------------------------------------
extern "C" void kernel_launch(void* const* d_in, const int* in_sizes, int n_in,
                              void* d_out, int out_size) {
    const float* x    = (const float*)d_in[0];
    const int*   src  = (const int*)  d_in[1];
    const int*   dst  = (const int*)  d_in[2];
    const float* Ws1  = (const float*)d_in[3];
    const float* Wn1  = (const float*)d_in[4];
    const float* b1   = (const float*)d_in[5];
    const float* ga1  = (const float*)d_in[6];
    const float* be1  = (const float*)d_in[7];
    const float* Ws2  = (const float*)d_in[8];
    const float* Wn2  = (const float*)d_in[9];
    const float* b2   = (const float*)d_in[10];
    const float* ga2  = (const float*)d_in[11];
    const float* be2  = (const float*)d_in[12];
    const float* Ws3  = (const float*)d_in[13];
    const float* Wn3  = (const float*)d_in[14];
    const float* b3   = (const float*)d_in[15];
    float* out = (float*)d_out;

    float *agg, *bufA, *bufB, *deg, *invdeg, *stats, *affine;
    cudaGetSymbolAddress((void**)&agg,    g_agg);
    cudaGetSymbolAddress((void**)&bufA,   g_bufA);
    cudaGetSymbolAddress((void**)&bufB,   g_bufB);
    cudaGetSymbolAddress((void**)&deg,    g_deg);
    cudaGetSymbolAddress((void**)&invdeg, g_invdeg);
    cudaGetSymbolAddress((void**)&stats,  g_stats);
    cudaGetSymbolAddress((void**)&affine, g_affine);

    const int FEAT4 = N_NODES * D / 4;           // 1.6M float4
    const int gemm_blocks = (N_NODES + 63) / 64; // 782
    const int scat_blocks = (N_EDGES * 32) / 256;

    // Degrees (once)
    zero_kernel<<<(N_NODES / 4 + 255) / 256, 256>>>((float4*)deg, N_NODES / 4);
    deg_kernel<<<(N_EDGES + 255) / 256, 256>>>(dst, deg);
    invdeg_kernel<<<(N_NODES + 255) / 256, 256>>>(deg, invdeg);

    // ---- Layer 1: x -> bufA
    zero_kernel<<<(FEAT4 + 255) / 256, 256>>>((float4*)agg, FEAT4);
    zero_kernel<<<1, 64>>>((float4*)stats, 64);
    scatter_kernel<<<scat_blocks, 256>>>(x, src, dst, agg);
    gemm_bn_kernel<<<gemm_blocks, 256>>>(x, agg, invdeg, Ws1, Wn1, b1, bufA, stats, 1);
    bn_finalize_kernel<<<1, 128>>>(stats, ga1, be1, affine);
    bn_apply_kernel<<<(N_NODES * 32 + 255) / 256, 256>>>((float4*)bufA, affine);

    // ---- Layer 2: bufA -> bufB
    zero_kernel<<<(FEAT4 + 255) / 256, 256>>>((float4*)agg, FEAT4);
    zero_kernel<<<1, 64>>>((float4*)stats, 64);
    scatter_kernel<<<scat_blocks, 256>>>(bufA, src, dst, agg);
    gemm_bn_kernel<<<gemm_blocks, 256>>>(bufA, agg, invdeg, Ws2, Wn2, b2, bufB, stats, 1);
    bn_finalize_kernel<<<1, 128>>>(stats, ga2, be2, affine);
    bn_apply_kernel<<<(N_NODES * 32 + 255) / 256, 256>>>((float4*)bufB, affine);

    // ---- Layer 3: bufB -> out (no BN)
    zero_kernel<<<(FEAT4 + 255) / 256, 256>>>((float4*)agg, FEAT4);
    scatter_kernel<<<scat_blocks, 256>>>(bufB, src, dst, agg);
    gemm_bn_kernel<<<gemm_blocks, 256>>>(bufB, agg, invdeg, Ws3, Wn3, b3, out, stats, 0);
}

// round 2
// speedup vs baseline: 1.2455x; 1.2455x over previous
#include <cuda_runtime.h>
#include <cstring>

#define N_NODES 50000
#define N_EDGES 800000
#define D 128
#define EPS 1e-5f

// Scratch (__device__ globals, allocation-free rule)
__device__ float g_bufA[N_NODES * D];
__device__ float g_bufB[N_NODES * D];
__device__ int   g_rowptr[N_NODES + 1];
__device__ int   g_cursor[N_NODES];     // also used as per-node count histogram
__device__ int   g_csrsrc[N_EDGES];
__device__ float g_invdeg[N_NODES];
__device__ float g_stats[2 * D];
__device__ float g_affine1[2 * D];
__device__ float g_affine2[2 * D];

// ---------------------------------------------------------------------------
__global__ void zero_int_kernel(int4* __restrict__ p, int n4) {
    int i = blockIdx.x * blockDim.x + threadIdx.x;
    if (i < n4) p[i] = make_int4(0, 0, 0, 0);
}

__global__ void hist_kernel(const int* __restrict__ dst, int* __restrict__ cnt) {
    int e = blockIdx.x * blockDim.x + threadIdx.x;
    if (e < N_EDGES) atomicAdd(&cnt[dst[e]], 1);
}

// Single-block exclusive scan of counts (thread-coarsened x4).
// Writes rowptr, cursor (= rowptr copy), invdeg, zeroes stats.
__global__ __launch_bounds__(1024) void scan_kernel(
    const int* __restrict__ cnt_in, int* __restrict__ rowptr,
    int* __restrict__ cursor, float* __restrict__ invdeg,
    float* __restrict__ stats)
{
    __shared__ int wsum[32];
    __shared__ int s_carry;
    const int t = threadIdx.x, lane = t & 31, w = t >> 5;
    if (t == 0) s_carry = 0;
    if (t < 2 * D) stats[t] = 0.f;
    __syncthreads();

    const int CHUNK = 4096;  // 1024 threads x 4
    for (int base = 0; base < N_NODES; base += CHUNK) {
        int i0 = base + t * 4;
        int v[4];
#pragma unroll
        for (int j = 0; j < 4; ++j)
            v[j] = (i0 + j < N_NODES) ? cnt_in[i0 + j] : 0;
        int tsum = v[0] + v[1] + v[2] + v[3];

        // inclusive warp scan of tsum
        int x = tsum;
#pragma unroll
        for (int o = 1; o < 32; o <<= 1) {
            int y = __shfl_up_sync(~0u, x, o);
            if (lane >= o) x += y;
        }
        if (lane == 31) wsum[w] = x;
        __syncthreads();
        if (w == 0) {
            int s = wsum[lane];
#pragma unroll
            for (int o = 1; o < 32; o <<= 1) {
                int y = __shfl_up_sync(~0u, s, o);
                if (lane >= o) s += y;
            }
            wsum[lane] = s;
        }
        __syncthreads();
        int woff = (w == 0) ? 0 : wsum[w - 1];
        int excl = s_carry + woff + (x - tsum);  // exclusive prefix for this thread's 4
        int run = excl;
#pragma unroll
        for (int j = 0; j < 4; ++j) {
            int i = i0 + j;
            if (i < N_NODES) {
                rowptr[i] = run;
                cursor[i] = run;
                invdeg[i] = 1.0f / fmaxf((float)v[j], 1.0f);
            }
            run += v[j];
        }
        __syncthreads();
        if (t == 1023) s_carry += wsum[31];
        __syncthreads();
    }
    if (t == 0) rowptr[N_NODES] = s_carry;
}

__global__ void fill_kernel(const int* __restrict__ src, const int* __restrict__ dst,
                            int* __restrict__ cursor, int* __restrict__ csrsrc) {
    int e = blockIdx.x * blockDim.x + threadIdx.x;
    if (e < N_EDGES) {
        int p = atomicAdd(&cursor[dst[e]], 1);
        csrsrc[p] = src[e];
    }
}

// ---------------------------------------------------------------------------
__device__ __forceinline__ void fma2(unsigned long long& acc,
                                     unsigned long long a, unsigned long long b) {
    asm("fma.rn.f32x2 %0, %1, %2, %0;" : "+l"(acc) : "l"(a), "l"(b));
}
__device__ __forceinline__ unsigned long long pk(float lo, float hi) {
    unsigned long long r;
    asm("mov.b64 %0, {%1, %2};" : "=l"(r) : "f"(lo), "f"(hi));
    return r;
}

// One 128-k GEMM pass over the 64x128 SMEM tile using k-pair packed FMA2.
__device__ __forceinline__ void mm_pass(const float* __restrict__ Xs,
                                        const float4* __restrict__ W4,
                                        int tx, int ty,
                                        unsigned long long acc[8][4]) {
#pragma unroll 4
    for (int kp = 0; kp < 64; ++kp) {
        float4 wa = __ldg(&W4[(2 * kp) * 32 + tx]);
        float4 wb = __ldg(&W4[(2 * kp + 1) * 32 + tx]);
        unsigned long long wp0 = pk(wa.x, wb.x);
        unsigned long long wp1 = pk(wa.y, wb.y);
        unsigned long long wp2 = pk(wa.z, wb.z);
        unsigned long long wp3 = pk(wa.w, wb.w);
#pragma unroll
        for (int r = 0; r < 8; ++r) {
            unsigned long long x2;
            memcpy(&x2, Xs + (ty * 8 + r) * 128 + 2 * kp, 8);
            fma2(acc[r][0], x2, wp0);
            fma2(acc[r][1], x2, wp1);
            fma2(acc[r][2], x2, wp2);
            fma2(acc[r][3], x2, wp3);
        }
    }
}

__device__ __forceinline__ float4 bn_relu4(float4 v, float4 sc, float4 sh) {
    v.x = fmaxf(fmaf(v.x, sc.x, sh.x), 0.f);
    v.y = fmaxf(fmaf(v.y, sc.y, sh.y), 0.f);
    v.z = fmaxf(fmaf(v.z, sc.z, sh.z), 0.f);
    v.w = fmaxf(fmaf(v.w, sc.w, sh.w), 0.f);
    return v;
}

// Fused layer: Out = BNrelu(Xin) @ Ws + mean_gather(BNrelu(X[nbrs])) @ Wn + b
// (BNrelu applied only if useAffine). Optionally accumulates BN stats of Out.
__global__ __launch_bounds__(256, 2) void sage_layer_kernel(
    const float* __restrict__ Xin,
    const float* __restrict__ affine, int useAffine,
    const int* __restrict__ rowptr,
    const int* __restrict__ csrsrc,
    const float* __restrict__ invdeg,
    const float4* __restrict__ Ws4,
    const float4* __restrict__ Wn4,
    const float* __restrict__ bias,
    float* __restrict__ Out,
    float* __restrict__ stats,
    int withBN)
{
    __shared__ float Xs[64 * 128];
    __shared__ float s_sum[128];
    __shared__ float s_sumsq[128];

    const int tid = threadIdx.x;
    const int tx = tid & 31;   // column group: cols 4*tx..4*tx+3
    const int ty = tid >> 5;   // warp id: rows 8*ty..8*ty+7
    const int row0 = blockIdx.x * 64;
    const float4* X4 = (const float4*)Xin;

    float4 sc = make_float4(1.f, 1.f, 1.f, 1.f);
    float4 sh = make_float4(0.f, 0.f, 0.f, 0.f);
    if (useAffine) {
        sc = __ldg(&((const float4*)affine)[tx]);
        sh = __ldg(&((const float4*)affine)[32 + tx]);
    }

    unsigned long long acc[8][4];
#pragma unroll
    for (int r = 0; r < 8; ++r)
#pragma unroll
        for (int c = 0; c < 4; ++c) acc[r][c] = 0ull;

    // ---- Phase A: self features into Xs (BN+ReLU applied if requested)
#pragma unroll
    for (int i = 0; i < 8; ++i) {
        int idx = tid + i * 256;     // r = idx>>5 (= ty + 8i), c = tx
        int r = idx >> 5;
        int gr = row0 + r;
        float4 v = make_float4(0.f, 0.f, 0.f, 0.f);
        if (gr < N_NODES) {
            v = X4[(size_t)gr * 32 + tx];
            if (useAffine) v = bn_relu4(v, sc, sh);
        }
        ((float4*)Xs)[idx] = v;
    }
    __syncthreads();
    mm_pass(Xs, Ws4, tx, ty, acc);
    __syncthreads();

    // ---- Phase B: mean-gather neighbor features into Xs
#pragma unroll
    for (int rr = 0; rr < 8; ++rr) {
        int gr = row0 + ty * 8 + rr;
        float4 a = make_float4(0.f, 0.f, 0.f, 0.f);
        if (gr < N_NODES) {
            int beg = __ldg(&rowptr[gr]);
            int end = __ldg(&rowptr[gr + 1]);
            float inv = __ldg(&invdeg[gr]);
            int p = beg;
            for (; p + 3 < end; p += 4) {
                int nb0 = __ldg(&csrsrc[p]);
                int nb1 = __ldg(&csrsrc[p + 1]);
                int nb2 = __ldg(&csrsrc[p + 2]);
                int nb3 = __ldg(&csrsrc[p + 3]);
                float4 v0 = X4[(size_t)nb0 * 32 + tx];
                float4 v1 = X4[(size_t)nb1 * 32 + tx];
                float4 v2 = X4[(size_t)nb2 * 32 + tx];
                float4 v3 = X4[(size_t)nb3 * 32 + tx];
                if (useAffine) {
                    v0 = bn_relu4(v0, sc, sh);
                    v1 = bn_relu4(v1, sc, sh);
                    v2 = bn_relu4(v2, sc, sh);
                    v3 = bn_relu4(v3, sc, sh);
                }
                a.x += v0.x + v1.x + v2.x + v3.x;
                a.y += v0.y + v1.y + v2.y + v3.y;
                a.z += v0.z + v1.z + v2.z + v3.z;
                a.w += v0.w + v1.w + v2.w + v3.w;
            }
            for (; p < end; ++p) {
                int nb = __ldg(&csrsrc[p]);
                float4 v = X4[(size_t)nb * 32 + tx];
                if (useAffine) v = bn_relu4(v, sc, sh);
                a.x += v.x; a.y += v.y; a.z += v.z; a.w += v.w;
            }
            a.x *= inv; a.y *= inv; a.z *= inv; a.w *= inv;
        }
        ((float4*)Xs)[(ty * 8 + rr) * 32 + tx] = a;
    }
    __syncthreads();
    mm_pass(Xs, Wn4, tx, ty, acc);

    // ---- Epilogue: bias, store, BN stats
    if (withBN && tid < 128) { s_sum[tid] = 0.f; s_sumsq[tid] = 0.f; }
    __syncthreads();

    float4 b4 = __ldg(&((const float4*)bias)[tx]);
    float ps[4] = {0.f, 0.f, 0.f, 0.f};
    float ps2[4] = {0.f, 0.f, 0.f, 0.f};

#pragma unroll
    for (int r = 0; r < 8; ++r) {
        int gr = row0 + ty * 8 + r;
        if (gr < N_NODES) {
            float2 f0, f1, f2, f3;
            memcpy(&f0, &acc[r][0], 8);
            memcpy(&f1, &acc[r][1], 8);
            memcpy(&f2, &acc[r][2], 8);
            memcpy(&f3, &acc[r][3], 8);
            float4 h;
            h.x = f0.x + f0.y + b4.x;
            h.y = f1.x + f1.y + b4.y;
            h.z = f2.x + f2.y + b4.z;
            h.w = f3.x + f3.y + b4.w;
            ((float4*)Out)[(size_t)gr * 32 + tx] = h;
            if (withBN) {
                ps[0] += h.x; ps2[0] += h.x * h.x;
                ps[1] += h.y; ps2[1] += h.y * h.y;
                ps[2] += h.z; ps2[2] += h.z * h.z;
                ps[3] += h.w; ps2[3] += h.w * h.w;
            }
        }
    }

    if (withBN) {
#pragma unroll
        for (int c = 0; c < 4; ++c) {
            atomicAdd(&s_sum[tx * 4 + c], ps[c]);
            atomicAdd(&s_sumsq[tx * 4 + c], ps2[c]);
        }
        __syncthreads();
        if (tid < 128) {
            atomicAdd(&stats[tid], s_sum[tid]);
            atomicAdd(&stats[128 + tid], s_sumsq[tid]);
        }
    }
}

// ---------------------------------------------------------------------------
// Finalize BN affine for this layer and re-zero stats for the next one.
__global__ void bn_finalize_kernel(float* __restrict__ stats,
                                   const float* __restrict__ gamma,
                                   const float* __restrict__ beta,
                                   float* __restrict__ affine) {
    int j = threadIdx.x;  // 128 threads
    const float invN = 1.0f / (float)N_NODES;
    float mu = stats[j] * invN;
    float var = stats[128 + j] * invN - mu * mu;
    float s = gamma[j] * rsqrtf(var + EPS);
    affine[j] = s;
    affine[128 + j] = beta[j] - mu * s;
    stats[j] = 0.f;
    stats[128 + j] = 0.f;
}

// ---------------------------------------------------------------------------
extern "C" void kernel_launch(void* const* d_in, const int* in_sizes, int n_in,
                              void* d_out, int out_size) {
    const float* x   = (const float*)d_in[0];
    const int*   src = (const int*)  d_in[1];
    const int*   dst = (const int*)  d_in[2];
    const float* Ws1 = (const float*)d_in[3];
    const float* Wn1 = (const float*)d_in[4];
    const float* b1  = (const float*)d_in[5];
    const float* ga1 = (const float*)d_in[6];
    const float* be1 = (const float*)d_in[7];
    const float* Ws2 = (const float*)d_in[8];
    const float* Wn2 = (const float*)d_in[9];
    const float* b2  = (const float*)d_in[10];
    const float* ga2 = (const float*)d_in[11];
    const float* be2 = (const float*)d_in[12];
    const float* Ws3 = (const float*)d_in[13];
    const float* Wn3 = (const float*)d_in[14];
    const float* b3  = (const float*)d_in[15];
    float* out = (float*)d_out;

    float *bufA, *bufB, *invdeg, *stats, *aff1, *aff2;
    int *rowptr, *cursor, *csrsrc;
    cudaGetSymbolAddress((void**)&bufA,   g_bufA);
    cudaGetSymbolAddress((void**)&bufB,   g_bufB);
    cudaGetSymbolAddress((void**)&rowptr, g_rowptr);
    cudaGetSymbolAddress((void**)&cursor, g_cursor);
    cudaGetSymbolAddress((void**)&csrsrc, g_csrsrc);
    cudaGetSymbolAddress((void**)&invdeg, g_invdeg);
    cudaGetSymbolAddress((void**)&stats,  g_stats);
    cudaGetSymbolAddress((void**)&aff1,   g_affine1);
    cudaGetSymbolAddress((void**)&aff2,   g_affine2);

    const int gemm_blocks = (N_NODES + 63) / 64;  // 782

    // Build CSR (counts -> scan -> fill); scan also zeroes stats.
    zero_int_kernel<<<(N_NODES / 4 + 255) / 256, 256>>>((int4*)cursor, N_NODES / 4);
    hist_kernel<<<(N_EDGES + 255) / 256, 256>>>(dst, cursor);
    scan_kernel<<<1, 1024>>>(cursor, rowptr, cursor, invdeg, stats);
    fill_kernel<<<(N_EDGES + 255) / 256, 256>>>(src, dst, cursor, csrsrc);

    // Layer 1: x -> bufA (raw input, BN stats on)
    sage_layer_kernel<<<gemm_blocks, 256>>>(x, nullptr, 0, rowptr, csrsrc, invdeg,
                                            (const float4*)Ws1, (const float4*)Wn1,
                                            b1, bufA, stats, 1);
    bn_finalize_kernel<<<1, 128>>>(stats, ga1, be1, aff1);

    // Layer 2: BNrelu(bufA) -> bufB (BN stats on)
    sage_layer_kernel<<<gemm_blocks, 256>>>(bufA, aff1, 1, rowptr, csrsrc, invdeg,
                                            (const float4*)Ws2, (const float4*)Wn2,
                                            b2, bufB, stats, 1);
    bn_finalize_kernel<<<1, 128>>>(stats, ga2, be2, aff2);

    // Layer 3: BNrelu(bufB) -> out (no BN)
    sage_layer_kernel<<<gemm_blocks, 256>>>(bufB, aff2, 1, rowptr, csrsrc, invdeg,
                                            (const float4*)Ws3, (const float4*)Wn3,
                                            b3, out, stats, 0);
}

// round 3
// speedup vs baseline: 1.2955x; 1.0401x over previous
#include <cuda_runtime.h>
#include <cstring>

#define N_NODES 50000
#define N_EDGES 800000
#define D 128
#define EPS 1e-5f

// Scratch (__device__ globals, allocation-free rule)
__device__ float g_bufA[N_NODES * D];
__device__ float g_bufB[N_NODES * D];
__device__ float g_agg[N_NODES * D];
__device__ int   g_rowptr[N_NODES + 1];
__device__ int   g_cursor[N_NODES];
__device__ int   g_csrsrc[N_EDGES];
__device__ float g_invdeg[N_NODES];
__device__ float g_stats[2 * D];
__device__ float g_affine1[2 * D];
__device__ float g_affine2[2 * D];

// ---------------------------------------------------------------------------
__global__ void zero_int_kernel(int4* __restrict__ p, int n4) {
    int i = blockIdx.x * blockDim.x + threadIdx.x;
    if (i < n4) p[i] = make_int4(0, 0, 0, 0);
}

__global__ void hist_kernel(const int* __restrict__ dst, int* __restrict__ cnt) {
    int e = blockIdx.x * blockDim.x + threadIdx.x;
    if (e < N_EDGES) atomicAdd(&cnt[dst[e]], 1);
}

// Single-block exclusive scan of counts (thread-coarsened x4).
__global__ __launch_bounds__(1024) void scan_kernel(
    const int* __restrict__ cnt_in, int* __restrict__ rowptr,
    int* __restrict__ cursor, float* __restrict__ invdeg,
    float* __restrict__ stats)
{
    __shared__ int wsum[32];
    __shared__ int s_carry;
    const int t = threadIdx.x, lane = t & 31, w = t >> 5;
    if (t == 0) s_carry = 0;
    if (t < 2 * D) stats[t] = 0.f;
    __syncthreads();

    const int CHUNK = 4096;
    for (int base = 0; base < N_NODES; base += CHUNK) {
        int i0 = base + t * 4;
        int v[4];
#pragma unroll
        for (int j = 0; j < 4; ++j)
            v[j] = (i0 + j < N_NODES) ? cnt_in[i0 + j] : 0;
        int tsum = v[0] + v[1] + v[2] + v[3];

        int x = tsum;
#pragma unroll
        for (int o = 1; o < 32; o <<= 1) {
            int y = __shfl_up_sync(~0u, x, o);
            if (lane >= o) x += y;
        }
        if (lane == 31) wsum[w] = x;
        __syncthreads();
        if (w == 0) {
            int s = wsum[lane];
#pragma unroll
            for (int o = 1; o < 32; o <<= 1) {
                int y = __shfl_up_sync(~0u, s, o);
                if (lane >= o) s += y;
            }
            wsum[lane] = s;
        }
        __syncthreads();
        int woff = (w == 0) ? 0 : wsum[w - 1];
        int run = s_carry + woff + (x - tsum);
#pragma unroll
        for (int j = 0; j < 4; ++j) {
            int i = i0 + j;
            if (i < N_NODES) {
                rowptr[i] = run;
                cursor[i] = run;
                invdeg[i] = 1.0f / fmaxf((float)v[j], 1.0f);
            }
            run += v[j];
        }
        __syncthreads();
        if (t == 1023) s_carry += wsum[31];
        __syncthreads();
    }
    if (t == 0) rowptr[N_NODES] = s_carry;
}

__global__ void fill_kernel(const int* __restrict__ src, const int* __restrict__ dst,
                            int* __restrict__ cursor, int* __restrict__ csrsrc) {
    int e = blockIdx.x * blockDim.x + threadIdx.x;
    if (e < N_EDGES) {
        int p = atomicAdd(&cursor[dst[e]], 1);
        csrsrc[p] = src[e];
    }
}

// ---------------------------------------------------------------------------
__device__ __forceinline__ float4 bn_relu4(float4 v, float4 sc, float4 sh) {
    v.x = fmaxf(fmaf(v.x, sc.x, sh.x), 0.f);
    v.y = fmaxf(fmaf(v.y, sc.y, sh.y), 0.f);
    v.z = fmaxf(fmaf(v.z, sc.z, sh.z), 0.f);
    v.w = fmaxf(fmaf(v.w, sc.w, sh.w), 0.f);
    return v;
}

// Warp-per-node mean gather: agg[n] = invdeg[n] * sum_{nb} BNrelu(X[nb]).
// Lane = float4 column -> every neighbor row is one coalesced 512B warp load.
__global__ __launch_bounds__(256) void gather_kernel(
    const float4* __restrict__ X4,
    const float* __restrict__ affine, int useAffine,
    const int* __restrict__ rowptr,
    const int* __restrict__ csrsrc,
    const float* __restrict__ invdeg,
    float4* __restrict__ agg)
{
    int gid = blockIdx.x * blockDim.x + threadIdx.x;
    int node = gid >> 5;
    if (node >= N_NODES) return;
    int lane = gid & 31;

    float4 sc = make_float4(1.f, 1.f, 1.f, 1.f);
    float4 sh = make_float4(0.f, 0.f, 0.f, 0.f);
    if (useAffine) {
        sc = __ldg(&((const float4*)affine)[lane]);
        sh = __ldg(&((const float4*)affine)[32 + lane]);
    }

    int beg = __ldg(&rowptr[node]);
    int end = __ldg(&rowptr[node + 1]);
    float inv = __ldg(&invdeg[node]);

    float4 a = make_float4(0.f, 0.f, 0.f, 0.f);
    int p = beg;
    // 8-deep unroll: 8 coalesced 512B row loads in flight per warp.
    for (; p + 7 < end; p += 8) {
        float4 v[8];
#pragma unroll
        for (int j = 0; j < 8; ++j) {
            int nb = __ldg(&csrsrc[p + j]);
            v[j] = X4[(size_t)nb * 32 + lane];
        }
#pragma unroll
        for (int j = 0; j < 8; ++j) {
            if (useAffine) v[j] = bn_relu4(v[j], sc, sh);
            a.x += v[j].x; a.y += v[j].y; a.z += v[j].z; a.w += v[j].w;
        }
    }
    for (; p < end; ++p) {
        int nb = __ldg(&csrsrc[p]);
        float4 v = X4[(size_t)nb * 32 + lane];
        if (useAffine) v = bn_relu4(v, sc, sh);
        a.x += v.x; a.y += v.y; a.z += v.z; a.w += v.w;
    }
    a.x *= inv; a.y *= inv; a.z *= inv; a.w *= inv;
    agg[(size_t)node * 32 + lane] = a;
}

// ---------------------------------------------------------------------------
__device__ __forceinline__ void fma2(unsigned long long& acc,
                                     unsigned long long a, unsigned long long b) {
    asm("fma.rn.f32x2 %0, %1, %2, %0;" : "+l"(acc) : "l"(a), "l"(b));
}
__device__ __forceinline__ unsigned long long pk(float lo, float hi) {
    unsigned long long r;
    asm("mov.b64 %0, {%1, %2};" : "=l"(r) : "f"(lo), "f"(hi));
    return r;
}

// One 128-k GEMM pass over the 64x128 SMEM tile using k-pair packed FMA2.
__device__ __forceinline__ void mm_pass(const float* __restrict__ Xs,
                                        const float4* __restrict__ W4,
                                        int tx, int ty,
                                        unsigned long long acc[8][4]) {
#pragma unroll 4
    for (int kp = 0; kp < 64; ++kp) {
        float4 wa = __ldg(&W4[(2 * kp) * 32 + tx]);
        float4 wb = __ldg(&W4[(2 * kp + 1) * 32 + tx]);
        unsigned long long wp0 = pk(wa.x, wb.x);
        unsigned long long wp1 = pk(wa.y, wb.y);
        unsigned long long wp2 = pk(wa.z, wb.z);
        unsigned long long wp3 = pk(wa.w, wb.w);
#pragma unroll
        for (int r = 0; r < 8; ++r) {
            unsigned long long x2;
            memcpy(&x2, Xs + (ty * 8 + r) * 128 + 2 * kp, 8);
            fma2(acc[r][0], x2, wp0);
            fma2(acc[r][1], x2, wp1);
            fma2(acc[r][2], x2, wp2);
            fma2(acc[r][3], x2, wp3);
        }
    }
}

// Dense fused GEMM: Out = BNrelu(Xin) @ Ws + Agg @ Wn + bias (+ BN stats).
__global__ __launch_bounds__(256, 2) void sage_gemm_kernel(
    const float* __restrict__ Xin,
    const float* __restrict__ Agg,
    const float* __restrict__ affine, int useAffine,
    const float4* __restrict__ Ws4,
    const float4* __restrict__ Wn4,
    const float* __restrict__ bias,
    float* __restrict__ Out,
    float* __restrict__ stats,
    int withBN)
{
    __shared__ float Xs[64 * 128];
    __shared__ float s_sum[128];
    __shared__ float s_sumsq[128];

    const int tid = threadIdx.x;
    const int tx = tid & 31;
    const int ty = tid >> 5;
    const int row0 = blockIdx.x * 64;

    float4 sc = make_float4(1.f, 1.f, 1.f, 1.f);
    float4 sh = make_float4(0.f, 0.f, 0.f, 0.f);
    if (useAffine) {
        sc = __ldg(&((const float4*)affine)[tx]);
        sh = __ldg(&((const float4*)affine)[32 + tx]);
    }

    unsigned long long acc[8][4];
#pragma unroll
    for (int r = 0; r < 8; ++r)
#pragma unroll
        for (int c = 0; c < 4; ++c) acc[r][c] = 0ull;

#pragma unroll
    for (int pass = 0; pass < 2; ++pass) {
        const float4* S4 = (const float4*)((pass == 0) ? Xin : Agg);
        const float4* W4 = (pass == 0) ? Ws4 : Wn4;

        __syncthreads();
#pragma unroll
        for (int i = 0; i < 8; ++i) {
            int idx = tid + i * 256;
            int r = idx >> 5;
            int gr = row0 + r;
            float4 v = make_float4(0.f, 0.f, 0.f, 0.f);
            if (gr < N_NODES) {
                v = S4[(size_t)gr * 32 + tx];
                if (pass == 0 && useAffine) v = bn_relu4(v, sc, sh);
            }
            ((float4*)Xs)[idx] = v;
        }
        __syncthreads();
        mm_pass(Xs, W4, tx, ty, acc);
    }

    if (withBN && tid < 128) { s_sum[tid] = 0.f; s_sumsq[tid] = 0.f; }
    __syncthreads();

    float4 b4 = __ldg(&((const float4*)bias)[tx]);
    float ps[4] = {0.f, 0.f, 0.f, 0.f};
    float ps2[4] = {0.f, 0.f, 0.f, 0.f};

#pragma unroll
    for (int r = 0; r < 8; ++r) {
        int gr = row0 + ty * 8 + r;
        if (gr < N_NODES) {
            float2 f0, f1, f2, f3;
            memcpy(&f0, &acc[r][0], 8);
            memcpy(&f1, &acc[r][1], 8);
            memcpy(&f2, &acc[r][2], 8);
            memcpy(&f3, &acc[r][3], 8);
            float4 h;
            h.x = f0.x + f0.y + b4.x;
            h.y = f1.x + f1.y + b4.y;
            h.z = f2.x + f2.y + b4.z;
            h.w = f3.x + f3.y + b4.w;
            ((float4*)Out)[(size_t)gr * 32 + tx] = h;
            if (withBN) {
                ps[0] += h.x; ps2[0] += h.x * h.x;
                ps[1] += h.y; ps2[1] += h.y * h.y;
                ps[2] += h.z; ps2[2] += h.z * h.z;
                ps[3] += h.w; ps2[3] += h.w * h.w;
            }
        }
    }

    if (withBN) {
#pragma unroll
        for (int c = 0; c < 4; ++c) {
            atomicAdd(&s_sum[tx * 4 + c], ps[c]);
            atomicAdd(&s_sumsq[tx * 4 + c], ps2[c]);
        }
        __syncthreads();
        if (tid < 128) {
            atomicAdd(&stats[tid], s_sum[tid]);
            atomicAdd(&stats[128 + tid], s_sumsq[tid]);
        }
    }
}

// ---------------------------------------------------------------------------
__global__ void bn_finalize_kernel(float* __restrict__ stats,
                                   const float* __restrict__ gamma,
                                   const float* __restrict__ beta,
                                   float* __restrict__ affine) {
    int j = threadIdx.x;
    const float invN = 1.0f / (float)N_NODES;
    float mu = stats[j] * invN;
    float var = stats[128 + j] * invN - mu * mu;
    float s = gamma[j] * rsqrtf(var + EPS);
    affine[j] = s;
    affine[128 + j] = beta[j] - mu * s;
    stats[j] = 0.f;
    stats[128 + j] = 0.f;
}

// ---------------------------------------------------------------------------
extern "C" void kernel_launch(void* const* d_in, const int* in_sizes, int n_in,
                              void* d_out, int out_size) {
    const float* x   = (const float*)d_in[0];
    const int*   src = (const int*)  d_in[1];
    const int*   dst = (const int*)  d_in[2];
    const float* Ws1 = (const float*)d_in[3];
    const float* Wn1 = (const float*)d_in[4];
    const float* b1  = (const float*)d_in[5];
    const float* ga1 = (const float*)d_in[6];
    const float* be1 = (const float*)d_in[7];
    const float* Ws2 = (const float*)d_in[8];
    const float* Wn2 = (const float*)d_in[9];
    const float* b2  = (const float*)d_in[10];
    const float* ga2 = (const float*)d_in[11];
    const float* be2 = (const float*)d_in[12];
    const float* Ws3 = (const float*)d_in[13];
    const float* Wn3 = (const float*)d_in[14];
    const float* b3  = (const float*)d_in[15];
    float* out = (float*)d_out;

    float *bufA, *bufB, *agg, *invdeg, *stats, *aff1, *aff2;
    int *rowptr, *cursor, *csrsrc;
    cudaGetSymbolAddress((void**)&bufA,   g_bufA);
    cudaGetSymbolAddress((void**)&bufB,   g_bufB);
    cudaGetSymbolAddress((void**)&agg,    g_agg);
    cudaGetSymbolAddress((void**)&rowptr, g_rowptr);
    cudaGetSymbolAddress((void**)&cursor, g_cursor);
    cudaGetSymbolAddress((void**)&csrsrc, g_csrsrc);
    cudaGetSymbolAddress((void**)&invdeg, g_invdeg);
    cudaGetSymbolAddress((void**)&stats,  g_stats);
    cudaGetSymbolAddress((void**)&aff1,   g_affine1);
    cudaGetSymbolAddress((void**)&aff2,   g_affine2);

    const int gemm_blocks = (N_NODES + 63) / 64;        // 782
    const int gthr_blocks = (N_NODES * 32 + 255) / 256; // 6250

    // Build CSR.
    zero_int_kernel<<<(N_NODES / 4 + 255) / 256, 256>>>((int4*)cursor, N_NODES / 4);
    hist_kernel<<<(N_EDGES + 255) / 256, 256>>>(dst, cursor);
    scan_kernel<<<1, 1024>>>(cursor, rowptr, cursor, invdeg, stats);
    fill_kernel<<<(N_EDGES + 255) / 256, 256>>>(src, dst, cursor, csrsrc);

    // Layer 1
    gather_kernel<<<gthr_blocks, 256>>>((const float4*)x, nullptr, 0,
                                        rowptr, csrsrc, invdeg, (float4*)agg);
    sage_gemm_kernel<<<gemm_blocks, 256>>>(x, agg, nullptr, 0,
                                           (const float4*)Ws1, (const float4*)Wn1,
                                           b1, bufA, stats, 1);
    bn_finalize_kernel<<<1, 128>>>(stats, ga1, be1, aff1);

    // Layer 2
    gather_kernel<<<gthr_blocks, 256>>>((const float4*)bufA, aff1, 1,
                                        rowptr, csrsrc, invdeg, (float4*)agg);
    sage_gemm_kernel<<<gemm_blocks, 256>>>(bufA, agg, aff1, 1,
                                           (const float4*)Ws2, (const float4*)Wn2,
                                           b2, bufB, stats, 1);
    bn_finalize_kernel<<<1, 128>>>(stats, ga2, be2, aff2);

    // Layer 3
    gather_kernel<<<gthr_blocks, 256>>>((const float4*)bufB, aff2, 1,
                                        rowptr, csrsrc, invdeg, (float4*)agg);
    sage_gemm_kernel<<<gemm_blocks, 256>>>(bufB, agg, aff2, 1,
                                           (const float4*)Ws3, (const float4*)Wn3,
                                           b3, out, stats, 0);
}

// round 5
// speedup vs baseline: 2.2257x; 1.7181x over previous
#include <cuda_runtime.h>
#include <cuda_bf16.h>
#include <cstdint>
#include <cstring>

#define N_NODES 50000
#define N_EDGES 800000
#define EPS 1e-5f

#define TILE_M 128
#define GEMM_BLOCKS ((N_NODES + TILE_M - 1) / TILE_M)

// SMEM layout (bytes): X hi/lo + W hi/lo bf16 tiles (each 128x128 bf16 = 32KB)
#define SM_XHI 0
#define SM_XLO 32768
#define SM_WHI 65536
#define SM_WLO 98304
#define SM_TOTAL 131072

// Scratch (__device__ globals, allocation-free rule)
__device__ float g_bufA[N_NODES * 128];
__device__ float g_bufB[N_NODES * 128];
__device__ float g_agg[N_NODES * 128];
__device__ int   g_rowptr[N_NODES + 1];
__device__ int   g_cursor[N_NODES];
__device__ int   g_csrsrc[N_EDGES];
__device__ float g_invdeg[N_NODES];
__device__ float g_stats[256];
__device__ float g_affine1[256];
__device__ float g_affine2[256];
// Pre-transposed + bf16-split weight images (2 passes: Ws, Wn), SMEM byte-image
__device__ uint4 g_wthi[2 * 2048];
__device__ uint4 g_wtlo[2 * 2048];

// ===========================================================================
// CSR build
// ===========================================================================
__global__ void zero_int_kernel(int4* __restrict__ p, int n4) {
    int i = blockIdx.x * blockDim.x + threadIdx.x;
    if (i < n4) p[i] = make_int4(0, 0, 0, 0);
}

__global__ void hist_kernel(const int* __restrict__ dst, int* __restrict__ cnt) {
    int e = blockIdx.x * blockDim.x + threadIdx.x;
    if (e < N_EDGES) atomicAdd(&cnt[dst[e]], 1);
}

__global__ __launch_bounds__(1024) void scan_kernel(
    const int* __restrict__ cnt_in, int* __restrict__ rowptr,
    int* __restrict__ cursor, float* __restrict__ invdeg,
    float* __restrict__ stats)
{
    __shared__ int wsum[32];
    __shared__ int s_carry;
    const int t = threadIdx.x, lane = t & 31, w = t >> 5;
    if (t == 0) s_carry = 0;
    if (t < 256) stats[t] = 0.f;
    __syncthreads();

    const int CHUNK = 4096;
    for (int base = 0; base < N_NODES; base += CHUNK) {
        int i0 = base + t * 4;
        int v[4];
#pragma unroll
        for (int j = 0; j < 4; ++j)
            v[j] = (i0 + j < N_NODES) ? cnt_in[i0 + j] : 0;
        int tsum = v[0] + v[1] + v[2] + v[3];

        int x = tsum;
#pragma unroll
        for (int o = 1; o < 32; o <<= 1) {
            int y = __shfl_up_sync(~0u, x, o);
            if (lane >= o) x += y;
        }
        if (lane == 31) wsum[w] = x;
        __syncthreads();
        if (w == 0) {
            int s = wsum[lane];
#pragma unroll
            for (int o = 1; o < 32; o <<= 1) {
                int y = __shfl_up_sync(~0u, s, o);
                if (lane >= o) s += y;
            }
            wsum[lane] = s;
        }
        __syncthreads();
        int woff = (w == 0) ? 0 : wsum[w - 1];
        int run = s_carry + woff + (x - tsum);
#pragma unroll
        for (int j = 0; j < 4; ++j) {
            int i = i0 + j;
            if (i < N_NODES) {
                rowptr[i] = run;
                cursor[i] = run;
                invdeg[i] = 1.0f / fmaxf((float)v[j], 1.0f);
            }
            run += v[j];
        }
        __syncthreads();
        if (t == 1023) s_carry += wsum[31];
        __syncthreads();
    }
    if (t == 0) rowptr[N_NODES] = s_carry;
}

__global__ void fill_kernel(const int* __restrict__ src, const int* __restrict__ dst,
                            int* __restrict__ cursor, int* __restrict__ csrsrc) {
    int e = blockIdx.x * blockDim.x + threadIdx.x;
    if (e < N_EDGES) {
        int p = atomicAdd(&cursor[dst[e]], 1);
        csrsrc[p] = src[e];
    }
}

// ===========================================================================
// Gather (warp per node, mean of BNrelu'd neighbor rows)
// ===========================================================================
__device__ __forceinline__ float4 bn_relu4(float4 v, float4 sc, float4 sh) {
    v.x = fmaxf(fmaf(v.x, sc.x, sh.x), 0.f);
    v.y = fmaxf(fmaf(v.y, sc.y, sh.y), 0.f);
    v.z = fmaxf(fmaf(v.z, sc.z, sh.z), 0.f);
    v.w = fmaxf(fmaf(v.w, sc.w, sh.w), 0.f);
    return v;
}

__global__ __launch_bounds__(256) void gather_kernel(
    const float4* __restrict__ X4,
    const float* __restrict__ affine, int useAffine,
    const int* __restrict__ rowptr,
    const int* __restrict__ csrsrc,
    const float* __restrict__ invdeg,
    float4* __restrict__ agg)
{
    int gid = blockIdx.x * blockDim.x + threadIdx.x;
    int node = gid >> 5;
    if (node >= N_NODES) return;
    int lane = gid & 31;

    float4 sc = make_float4(1.f, 1.f, 1.f, 1.f);
    float4 sh = make_float4(0.f, 0.f, 0.f, 0.f);
    if (useAffine) {
        sc = __ldg(&((const float4*)affine)[lane]);
        sh = __ldg(&((const float4*)affine)[32 + lane]);
    }

    int beg = __ldg(&rowptr[node]);
    int end = __ldg(&rowptr[node + 1]);
    float inv = __ldg(&invdeg[node]);

    float4 a = make_float4(0.f, 0.f, 0.f, 0.f);
    int p = beg;
    for (; p + 7 < end; p += 8) {
        float4 v[8];
#pragma unroll
        for (int j = 0; j < 8; ++j) {
            int nb = __ldg(&csrsrc[p + j]);
            v[j] = X4[(size_t)nb * 32 + lane];
        }
#pragma unroll
        for (int j = 0; j < 8; ++j) {
            if (useAffine) v[j] = bn_relu4(v[j], sc, sh);
            a.x += v[j].x; a.y += v[j].y; a.z += v[j].z; a.w += v[j].w;
        }
    }
    for (; p < end; ++p) {
        int nb = __ldg(&csrsrc[p]);
        float4 v = X4[(size_t)nb * 32 + lane];
        if (useAffine) v = bn_relu4(v, sc, sh);
        a.x += v.x; a.y += v.y; a.z += v.z; a.w += v.w;
    }
    a.x *= inv; a.y *= inv; a.z *= inv; a.w *= inv;
    agg[(size_t)node * 32 + lane] = a;
}

// ===========================================================================
// bf16 split helpers
// ===========================================================================
__device__ __forceinline__ uint32_t pkbf(float a, float b) {
    __nv_bfloat162 h = __float22bfloat162_rn(make_float2(a, b));
    uint32_t r;
    memcpy(&r, &h, 4);
    return r;
}
__device__ __forceinline__ float bfhi(float a) {
    return __bfloat162float(__float2bfloat16_rn(a));
}

// Swizzled byte offset within a 128-row x 256B tile.
__device__ __forceinline__ uint32_t soff(int r, int byte) {
    return (uint32_t)(r * 256 + (byte ^ ((r & 7) << 4)));
}

// Build swizzled SMEM byte-image of W^T (hi/lo bf16) for both passes.
// idx: pass(1b) | n(7b) | chunk(4b); chunk = 8 consecutive k values.
__global__ void wprep_kernel(const float* __restrict__ Ws,
                             const float* __restrict__ Wn,
                             uint4* __restrict__ whi, uint4* __restrict__ wlo) {
    int idx = blockIdx.x * blockDim.x + threadIdx.x;
    if (idx >= 4096) return;
    int pass = idx >> 11;
    int n = (idx >> 4) & 127;
    int ch = idx & 15;
    const float* W = pass ? Wn : Ws;
    float v[8], h[8];
#pragma unroll
    for (int j = 0; j < 8; ++j) {
        v[j] = __ldg(&W[(ch * 8 + j) * 128 + n]);
        h[j] = bfhi(v[j]);
    }
    uint4 hi4, lo4;
    hi4.x = pkbf(h[0], h[1]); hi4.y = pkbf(h[2], h[3]);
    hi4.z = pkbf(h[4], h[5]); hi4.w = pkbf(h[6], h[7]);
    lo4.x = pkbf(v[0] - h[0], v[1] - h[1]);
    lo4.y = pkbf(v[2] - h[2], v[3] - h[3]);
    lo4.z = pkbf(v[4] - h[4], v[5] - h[5]);
    lo4.w = pkbf(v[6] - h[6], v[7] - h[7]);
    uint32_t off = (uint32_t)pass * 32768 + soff(n, ch * 16);
    *(uint4*)((char*)whi + off) = hi4;
    *(uint4*)((char*)wlo + off) = lo4;
}

// ===========================================================================
// mma.sync helpers (compute_103-safe)
// ===========================================================================
__device__ __forceinline__ uint32_t smem_u32(const void* p) {
    uint32_t a;
    asm("{ .reg .u64 t; cvta.to.shared.u64 t, %1; cvt.u32.u64 %0, t; }"
        : "=r"(a) : "l"(p));
    return a;
}

__device__ __forceinline__ void ldsm4(uint32_t& r0, uint32_t& r1,
                                      uint32_t& r2, uint32_t& r3, uint32_t addr) {
    asm volatile("ldmatrix.sync.aligned.m8n8.x4.shared.b16 {%0,%1,%2,%3}, [%4];"
                 : "=r"(r0), "=r"(r1), "=r"(r2), "=r"(r3) : "r"(addr));
}

__device__ __forceinline__ void mma16816(float* c, uint32_t a0, uint32_t a1,
                                         uint32_t a2, uint32_t a3,
                                         uint32_t b0, uint32_t b1) {
    asm volatile(
        "mma.sync.aligned.m16n8k16.row.col.f32.bf16.bf16.f32 "
        "{%0,%1,%2,%3}, {%4,%5,%6,%7}, {%8,%9}, {%0,%1,%2,%3};"
        : "+f"(c[0]), "+f"(c[1]), "+f"(c[2]), "+f"(c[3])
        : "r"(a0), "r"(a1), "r"(a2), "r"(a3), "r"(b0), "r"(b1));
}

// ===========================================================================
// Fused SAGE layer GEMM on tensor cores (mma.sync bf16, 3-term split):
// Out = BNrelu(Xin) @ Ws + Agg @ Wn + bias
// 512 threads: warp w -> rows (w&7)*16..+15, cols (w>>3)*64..+63
// ===========================================================================
__global__ __launch_bounds__(512, 1) void sage_mma_kernel(
    const float4* __restrict__ Xin4,
    const float4* __restrict__ Agg4,
    const float* __restrict__ affine, int useAffine,
    const uint4* __restrict__ wthi,
    const uint4* __restrict__ wtlo,
    const float* __restrict__ bias,
    float2* __restrict__ Out2)
{
    extern __shared__ char smem[];
    const uint32_t sbase = smem_u32(smem);
    const int tid = threadIdx.x;
    const int w = tid >> 5;
    const int lane = tid & 31;
    const int row0 = blockIdx.x * TILE_M;
    const int m0 = (w & 7) * 16;
    const int nhalf = w >> 3;

    float acc[8][4];
#pragma unroll
    for (int nt = 0; nt < 8; ++nt)
#pragma unroll
        for (int q = 0; q < 4; ++q) acc[nt][q] = 0.f;

    // Per-lane ldmatrix address bases
    const int aRow = m0 + (lane & 15);
    const uint32_t aBase = sbase + SM_XHI + (uint32_t)aRow * 256;
    const uint32_t aXor = (uint32_t)(aRow & 7) << 4;
    const uint32_t aSel = ((lane >> 4) & 1) * 16;

    uint32_t bBase[4], bXor[4];
#pragma unroll
    for (int ntp = 0; ntp < 4; ++ntp) {
        int bRow = nhalf * 64 + ntp * 16 + ((lane >> 4) & 1) * 8 + (lane & 7);
        bBase[ntp] = sbase + SM_WHI + (uint32_t)bRow * 256;
        bXor[ntp] = (uint32_t)(bRow & 7) << 4;
    }
    const uint32_t bSel = ((lane >> 3) & 1) * 16;

#pragma unroll
    for (int pass = 0; pass < 2; ++pass) {
        const float4* S4 = (pass == 0) ? Xin4 : Agg4;

        __syncthreads();  // protect SMEM from previous pass readers

        // ---- Fill X tile: 128 rows x 16 chunks (16B bf16 = 8 k-values)
#pragma unroll
        for (int it = 0; it < 4; ++it) {
            int idx = tid + it * 512;     // 0..2047
            int m = idx >> 4;
            int ch = idx & 15;
            int gr = row0 + m;
            float4 v0 = make_float4(0.f, 0.f, 0.f, 0.f);
            float4 v1 = v0;
            if (gr < N_NODES) {
                v0 = S4[(size_t)gr * 32 + ch * 2];
                v1 = S4[(size_t)gr * 32 + ch * 2 + 1];
                if (pass == 0 && useAffine) {
                    float4 sc0 = __ldg(&((const float4*)affine)[ch * 2]);
                    float4 sc1 = __ldg(&((const float4*)affine)[ch * 2 + 1]);
                    float4 sh0 = __ldg(&((const float4*)affine)[32 + ch * 2]);
                    float4 sh1 = __ldg(&((const float4*)affine)[32 + ch * 2 + 1]);
                    v0 = bn_relu4(v0, sc0, sh0);
                    v1 = bn_relu4(v1, sc1, sh1);
                }
            }
            float h0 = bfhi(v0.x), h1 = bfhi(v0.y), h2 = bfhi(v0.z), h3 = bfhi(v0.w);
            float h4 = bfhi(v1.x), h5 = bfhi(v1.y), h6 = bfhi(v1.z), h7 = bfhi(v1.w);
            uint4 hi4, lo4;
            hi4.x = pkbf(h0, h1); hi4.y = pkbf(h2, h3);
            hi4.z = pkbf(h4, h5); hi4.w = pkbf(h6, h7);
            lo4.x = pkbf(v0.x - h0, v0.y - h1);
            lo4.y = pkbf(v0.z - h2, v0.w - h3);
            lo4.z = pkbf(v1.x - h4, v1.y - h5);
            lo4.w = pkbf(v1.z - h6, v1.w - h7);
            uint32_t off = soff(m, ch * 16);
            *(uint4*)(smem + SM_XHI + off) = hi4;
            *(uint4*)(smem + SM_XLO + off) = lo4;
        }

        // ---- Copy W image (hi/lo, 32KB each) for this pass
        {
            const uint4* srcH = wthi + pass * 2048;
            const uint4* srcL = wtlo + pass * 2048;
#pragma unroll
            for (int it = 0; it < 4; ++it) {
                int idx = tid + it * 512;
                ((uint4*)(smem + SM_WHI))[idx] = __ldg(&srcH[idx]);
                ((uint4*)(smem + SM_WLO))[idx] = __ldg(&srcL[idx]);
            }
        }
        __syncthreads();

        // ---- MMA main loop: 8 k-steps, 4 n-tile pairs, 3 split terms
#pragma unroll
        for (int ks = 0; ks < 8; ++ks) {
            uint32_t aoff = ((uint32_t)(ks * 32) + aSel) ^ aXor;
            uint32_t ah0, ah1, ah2, ah3, al0, al1, al2, al3;
            ldsm4(ah0, ah1, ah2, ah3, aBase + aoff);
            ldsm4(al0, al1, al2, al3, aBase + 32768 + aoff);
#pragma unroll
            for (int ntp = 0; ntp < 4; ++ntp) {
                uint32_t boff = ((uint32_t)(ks * 32) + bSel) ^ bXor[ntp];
                uint32_t bh0, bh1, bh2, bh3, bl0, bl1, bl2, bl3;
                ldsm4(bh0, bh1, bh2, bh3, bBase[ntp] + boff);
                ldsm4(bl0, bl1, bl2, bl3, bBase[ntp] + 32768 + boff);
                // n-tile 2*ntp
                mma16816(acc[2 * ntp], ah0, ah1, ah2, ah3, bh0, bh1);
                mma16816(acc[2 * ntp], ah0, ah1, ah2, ah3, bl0, bl1);
                mma16816(acc[2 * ntp], al0, al1, al2, al3, bh0, bh1);
                // n-tile 2*ntp+1
                mma16816(acc[2 * ntp + 1], ah0, ah1, ah2, ah3, bh2, bh3);
                mma16816(acc[2 * ntp + 1], ah0, ah1, ah2, ah3, bl2, bl3);
                mma16816(acc[2 * ntp + 1], al0, al1, al2, al3, bh2, bh3);
            }
        }
    }

    // ---- Epilogue: bias + store
    {
        int g = lane >> 2;
        int i = lane & 3;
        int grA = row0 + m0 + g;
        int grB = grA + 8;
#pragma unroll
        for (int nt = 0; nt < 8; ++nt) {
            int col = nhalf * 64 + nt * 8 + 2 * i;
            float2 bv = __ldg(&((const float2*)bias)[col >> 1]);
            if (grA < N_NODES) {
                float2 o = make_float2(acc[nt][0] + bv.x, acc[nt][1] + bv.y);
                Out2[(size_t)grA * 64 + (col >> 1)] = o;
            }
            if (grB < N_NODES) {
                float2 o = make_float2(acc[nt][2] + bv.x, acc[nt][3] + bv.y);
                Out2[(size_t)grB * 64 + (col >> 1)] = o;
            }
        }
    }
}

// ===========================================================================
// BN stats + finalize
// ===========================================================================
__global__ __launch_bounds__(256) void bn_stats_kernel(const float4* __restrict__ H,
                                                       float* __restrict__ stats) {
    __shared__ float ss[256];
    int tid = threadIdx.x;
    int w = tid >> 5, lane = tid & 31;
    ss[tid] = 0.f;
    __syncthreads();

    float s[4] = {0.f, 0.f, 0.f, 0.f};
    float q[4] = {0.f, 0.f, 0.f, 0.f};
    for (int row = blockIdx.x * 8 + w; row < N_NODES; row += gridDim.x * 8) {
        float4 v = H[(size_t)row * 32 + lane];
        s[0] += v.x; q[0] += v.x * v.x;
        s[1] += v.y; q[1] += v.y * v.y;
        s[2] += v.z; q[2] += v.z * v.z;
        s[3] += v.w; q[3] += v.w * v.w;
    }
#pragma unroll
    for (int j = 0; j < 4; ++j) {
        atomicAdd(&ss[lane * 4 + j], s[j]);
        atomicAdd(&ss[128 + lane * 4 + j], q[j]);
    }
    __syncthreads();
    atomicAdd(&stats[tid], ss[tid]);
}

__global__ void bn_finalize_kernel(float* __restrict__ stats,
                                   const float* __restrict__ gamma,
                                   const float* __restrict__ beta,
                                   float* __restrict__ affine) {
    int j = threadIdx.x;  // 128 threads
    const float invN = 1.0f / (float)N_NODES;
    float mu = stats[j] * invN;
    float var = stats[128 + j] * invN - mu * mu;
    float s = gamma[j] * rsqrtf(var + EPS);
    affine[j] = s;
    affine[128 + j] = beta[j] - mu * s;
    stats[j] = 0.f;
    stats[128 + j] = 0.f;
}

// ===========================================================================
extern "C" void kernel_launch(void* const* d_in, const int* in_sizes, int n_in,
                              void* d_out, int out_size) {
    const float* x   = (const float*)d_in[0];
    const int*   src = (const int*)  d_in[1];
    const int*   dst = (const int*)  d_in[2];
    const float* Ws1 = (const float*)d_in[3];
    const float* Wn1 = (const float*)d_in[4];
    const float* b1  = (const float*)d_in[5];
    const float* ga1 = (const float*)d_in[6];
    const float* be1 = (const float*)d_in[7];
    const float* Ws2 = (const float*)d_in[8];
    const float* Wn2 = (const float*)d_in[9];
    const float* b2  = (const float*)d_in[10];
    const float* ga2 = (const float*)d_in[11];
    const float* be2 = (const float*)d_in[12];
    const float* Ws3 = (const float*)d_in[13];
    const float* Wn3 = (const float*)d_in[14];
    const float* b3  = (const float*)d_in[15];
    float* out = (float*)d_out;

    float *bufA, *bufB, *agg, *invdeg, *stats, *aff1, *aff2;
    int *rowptr, *cursor, *csrsrc;
    uint4 *wthi, *wtlo;
    cudaGetSymbolAddress((void**)&bufA,   g_bufA);
    cudaGetSymbolAddress((void**)&bufB,   g_bufB);
    cudaGetSymbolAddress((void**)&agg,    g_agg);
    cudaGetSymbolAddress((void**)&rowptr, g_rowptr);
    cudaGetSymbolAddress((void**)&cursor, g_cursor);
    cudaGetSymbolAddress((void**)&csrsrc, g_csrsrc);
    cudaGetSymbolAddress((void**)&invdeg, g_invdeg);
    cudaGetSymbolAddress((void**)&stats,  g_stats);
    cudaGetSymbolAddress((void**)&aff1,   g_affine1);
    cudaGetSymbolAddress((void**)&aff2,   g_affine2);
    cudaGetSymbolAddress((void**)&wthi,   g_wthi);
    cudaGetSymbolAddress((void**)&wtlo,   g_wtlo);

    cudaFuncSetAttribute(sage_mma_kernel,
                         cudaFuncAttributeMaxDynamicSharedMemorySize, SM_TOTAL);

    const int gthr_blocks = (N_NODES * 32 + 255) / 256;

    // Build CSR (scan also zeroes stats).
    zero_int_kernel<<<(N_NODES / 4 + 255) / 256, 256>>>((int4*)cursor, N_NODES / 4);
    hist_kernel<<<(N_EDGES + 255) / 256, 256>>>(dst, cursor);
    scan_kernel<<<1, 1024>>>(cursor, rowptr, cursor, invdeg, stats);
    fill_kernel<<<(N_EDGES + 255) / 256, 256>>>(src, dst, cursor, csrsrc);

    // Layer 1
    wprep_kernel<<<16, 256>>>(Ws1, Wn1, wthi, wtlo);
    gather_kernel<<<gthr_blocks, 256>>>((const float4*)x, nullptr, 0,
                                        rowptr, csrsrc, invdeg, (float4*)agg);
    sage_mma_kernel<<<GEMM_BLOCKS, 512, SM_TOTAL>>>(
        (const float4*)x, (const float4*)agg, nullptr, 0, wthi, wtlo, b1, (float2*)bufA);
    bn_stats_kernel<<<256, 256>>>((const float4*)bufA, stats);
    bn_finalize_kernel<<<1, 128>>>(stats, ga1, be1, aff1);

    // Layer 2
    wprep_kernel<<<16, 256>>>(Ws2, Wn2, wthi, wtlo);
    gather_kernel<<<gthr_blocks, 256>>>((const float4*)bufA, aff1, 1,
                                        rowptr, csrsrc, invdeg, (float4*)agg);
    sage_mma_kernel<<<GEMM_BLOCKS, 512, SM_TOTAL>>>(
        (const float4*)bufA, (const float4*)agg, aff1, 1, wthi, wtlo, b2, (float2*)bufB);
    bn_stats_kernel<<<256, 256>>>((const float4*)bufB, stats);
    bn_finalize_kernel<<<1, 128>>>(stats, ga2, be2, aff2);

    // Layer 3
    wprep_kernel<<<16, 256>>>(Ws3, Wn3, wthi, wtlo);
    gather_kernel<<<gthr_blocks, 256>>>((const float4*)bufB, aff2, 1,
                                        rowptr, csrsrc, invdeg, (float4*)agg);
    sage_mma_kernel<<<GEMM_BLOCKS, 512, SM_TOTAL>>>(
        (const float4*)bufB, (const float4*)agg, aff2, 1, wthi, wtlo, b3, (float2*)out);
}

// round 7
// speedup vs baseline: 2.4962x; 1.1215x over previous
#include <cuda_runtime.h>
#include <cuda_bf16.h>
#include <cstdint>
#include <cstring>

#define N_NODES 50000
#define N_EDGES 800000
#define EPS 1e-5f

#define TILE_M 128
#define GEMM_BLOCKS ((N_NODES + TILE_M - 1) / TILE_M)

// SMEM layout (bytes)
#define SM_XHI 0
#define SM_XLO 32768
#define SM_WHI 65536
#define SM_WLO 98304
#define SM_STATS 131072
#define SM_TOTAL (131072 + 1024)

// Scratch (__device__ globals, allocation-free rule)
// NOTE: split-bf16 row = 128 bf16 = 256 B = 16 uint4 per node.
__device__ float g_bufA[N_NODES * 128];
__device__ float g_bufB[N_NODES * 128];
__device__ uint4 g_xhi[N_NODES * 16];   // split bf16 activations (hi), 256B/row
__device__ uint4 g_xlo[N_NODES * 16];
__device__ uint4 g_agghi[N_NODES * 16]; // split bf16 aggregates
__device__ uint4 g_agglo[N_NODES * 16];
__device__ int   g_rowptr[N_NODES + 1];
__device__ int   g_cursor[N_NODES];
__device__ int   g_csrsrc[N_EDGES];
__device__ float g_invdeg[N_NODES];
__device__ float g_stats[256];
__device__ float g_affine1[256];
__device__ float g_affine2[256];
__device__ uint4 g_wthi[2 * 2048];
__device__ uint4 g_wtlo[2 * 2048];

// ===========================================================================
// CSR build
// ===========================================================================
__global__ void zero_int_kernel(int4* __restrict__ p, int n4) {
    int i = blockIdx.x * blockDim.x + threadIdx.x;
    if (i < n4) p[i] = make_int4(0, 0, 0, 0);
}

__global__ void hist_kernel(const int* __restrict__ dst, int* __restrict__ cnt) {
    int e = blockIdx.x * blockDim.x + threadIdx.x;
    if (e < N_EDGES) atomicAdd(&cnt[dst[e]], 1);
}

__global__ __launch_bounds__(1024) void scan_kernel(
    const int* __restrict__ cnt_in, int* __restrict__ rowptr,
    int* __restrict__ cursor, float* __restrict__ invdeg,
    float* __restrict__ stats)
{
    __shared__ int wsum[32];
    __shared__ int s_carry;
    const int t = threadIdx.x, lane = t & 31, w = t >> 5;
    if (t == 0) s_carry = 0;
    if (t < 256) stats[t] = 0.f;
    __syncthreads();

    const int CHUNK = 4096;
    for (int base = 0; base < N_NODES; base += CHUNK) {
        int i0 = base + t * 4;
        int v[4];
#pragma unroll
        for (int j = 0; j < 4; ++j)
            v[j] = (i0 + j < N_NODES) ? cnt_in[i0 + j] : 0;
        int tsum = v[0] + v[1] + v[2] + v[3];

        int x = tsum;
#pragma unroll
        for (int o = 1; o < 32; o <<= 1) {
            int y = __shfl_up_sync(~0u, x, o);
            if (lane >= o) x += y;
        }
        if (lane == 31) wsum[w] = x;
        __syncthreads();
        if (w == 0) {
            int s = wsum[lane];
#pragma unroll
            for (int o = 1; o < 32; o <<= 1) {
                int y = __shfl_up_sync(~0u, s, o);
                if (lane >= o) s += y;
            }
            wsum[lane] = s;
        }
        __syncthreads();
        int woff = (w == 0) ? 0 : wsum[w - 1];
        int run = s_carry + woff + (x - tsum);
#pragma unroll
        for (int j = 0; j < 4; ++j) {
            int i = i0 + j;
            if (i < N_NODES) {
                rowptr[i] = run;
                cursor[i] = run;
                invdeg[i] = 1.0f / fmaxf((float)v[j], 1.0f);
            }
            run += v[j];
        }
        __syncthreads();
        if (t == 1023) s_carry += wsum[31];
        __syncthreads();
    }
    if (t == 0) rowptr[N_NODES] = s_carry;
}

__global__ void fill_kernel(const int* __restrict__ src, const int* __restrict__ dst,
                            int* __restrict__ cursor, int* __restrict__ csrsrc) {
    int e = blockIdx.x * blockDim.x + threadIdx.x;
    if (e < N_EDGES) {
        int p = atomicAdd(&cursor[dst[e]], 1);
        csrsrc[p] = src[e];
    }
}

// ===========================================================================
// bf16 helpers
// ===========================================================================
__device__ __forceinline__ uint32_t pkbf(float a, float b) {
    __nv_bfloat162 h = __float22bfloat162_rn(make_float2(a, b));
    uint32_t r;
    memcpy(&r, &h, 4);
    return r;
}
__device__ __forceinline__ float bfhi(float a) {
    return __bfloat162float(__float2bfloat16_rn(a));
}
__device__ __forceinline__ float2 bf2f(uint32_t u) {
    __nv_bfloat162 b;
    memcpy(&b, &u, 4);
    return __bfloat1622float2(b);
}
__device__ __forceinline__ float4 bn_relu4(float4 v, float4 sc, float4 sh) {
    v.x = fmaxf(fmaf(v.x, sc.x, sh.x), 0.f);
    v.y = fmaxf(fmaf(v.y, sc.y, sh.y), 0.f);
    v.z = fmaxf(fmaf(v.z, sc.z, sh.z), 0.f);
    v.w = fmaxf(fmaf(v.w, sc.w, sh.w), 0.f);
    return v;
}

// Swizzled byte offset within a 128-row x 256B tile.
__device__ __forceinline__ uint32_t soff(int r, int byte) {
    return (uint32_t)(r * 256 + (byte ^ ((r & 7) << 4)));
}

// ===========================================================================
// prep: Xhi/Xlo = split_bf16(BNrelu(H))  (one pass per layer)
// ===========================================================================
__global__ __launch_bounds__(256) void prep_kernel(
    const float4* __restrict__ H,
    const float* __restrict__ affine, int useAffine,
    uint2* __restrict__ xhi, uint2* __restrict__ xlo)
{
    int gid = blockIdx.x * blockDim.x + threadIdx.x;
    if (gid >= N_NODES * 32) return;
    float4 v = H[gid];
    if (useAffine) {
        int c = gid & 31;
        float4 sc = __ldg(&((const float4*)affine)[c]);
        float4 sh = __ldg(&((const float4*)affine)[32 + c]);
        v = bn_relu4(v, sc, sh);
    }
    float h0 = bfhi(v.x), h1 = bfhi(v.y), h2 = bfhi(v.z), h3 = bfhi(v.w);
    xhi[gid] = make_uint2(pkbf(h0, h1), pkbf(h2, h3));
    xlo[gid] = make_uint2(pkbf(v.x - h0, v.y - h1), pkbf(v.z - h2, v.w - h3));
}

// ===========================================================================
// Gather (warp per node, bf16-hi inputs, fp32 accumulate, split-bf16 output)
// ===========================================================================
__global__ __launch_bounds__(256) void gather_kernel(
    const uint2* __restrict__ xhi,
    const int* __restrict__ rowptr,
    const int* __restrict__ csrsrc,
    const float* __restrict__ invdeg,
    uint2* __restrict__ agghi, uint2* __restrict__ agglo)
{
    int gid = blockIdx.x * blockDim.x + threadIdx.x;
    int node = gid >> 5;
    if (node >= N_NODES) return;
    int lane = gid & 31;

    int beg = __ldg(&rowptr[node]);
    int end = __ldg(&rowptr[node + 1]);
    float inv = __ldg(&invdeg[node]);

    float a0 = 0.f, a1 = 0.f, a2 = 0.f, a3 = 0.f;
    int p = beg;
    for (; p + 7 < end; p += 8) {
        uint2 d[8];
#pragma unroll
        for (int j = 0; j < 8; ++j) {
            int nb = __ldg(&csrsrc[p + j]);
            d[j] = __ldg(&xhi[nb * 32 + lane]);
        }
#pragma unroll
        for (int j = 0; j < 8; ++j) {
            float2 f0 = bf2f(d[j].x), f1 = bf2f(d[j].y);
            a0 += f0.x; a1 += f0.y; a2 += f1.x; a3 += f1.y;
        }
    }
    for (; p + 3 < end; p += 4) {
        uint2 d[4];
#pragma unroll
        for (int j = 0; j < 4; ++j) {
            int nb = __ldg(&csrsrc[p + j]);
            d[j] = __ldg(&xhi[nb * 32 + lane]);
        }
#pragma unroll
        for (int j = 0; j < 4; ++j) {
            float2 f0 = bf2f(d[j].x), f1 = bf2f(d[j].y);
            a0 += f0.x; a1 += f0.y; a2 += f1.x; a3 += f1.y;
        }
    }
    for (; p < end; ++p) {
        int nb = __ldg(&csrsrc[p]);
        uint2 d = __ldg(&xhi[nb * 32 + lane]);
        float2 f0 = bf2f(d.x), f1 = bf2f(d.y);
        a0 += f0.x; a1 += f0.y; a2 += f1.x; a3 += f1.y;
    }
    a0 *= inv; a1 *= inv; a2 *= inv; a3 *= inv;
    float h0 = bfhi(a0), h1 = bfhi(a1), h2 = bfhi(a2), h3 = bfhi(a3);
    agghi[node * 32 + lane] = make_uint2(pkbf(h0, h1), pkbf(h2, h3));
    agglo[node * 32 + lane] = make_uint2(pkbf(a0 - h0, a1 - h1), pkbf(a2 - h2, a3 - h3));
}

// ===========================================================================
// W prep: swizzled SMEM byte-image of W^T (hi/lo bf16) for both passes.
// ===========================================================================
__global__ void wprep_kernel(const float* __restrict__ Ws,
                             const float* __restrict__ Wn,
                             uint4* __restrict__ whi, uint4* __restrict__ wlo) {
    int idx = blockIdx.x * blockDim.x + threadIdx.x;
    if (idx >= 4096) return;
    int pass = idx >> 11;
    int n = (idx >> 4) & 127;
    int ch = idx & 15;
    const float* W = pass ? Wn : Ws;
    float v[8], h[8];
#pragma unroll
    for (int j = 0; j < 8; ++j) {
        v[j] = __ldg(&W[(ch * 8 + j) * 128 + n]);
        h[j] = bfhi(v[j]);
    }
    uint4 hi4, lo4;
    hi4.x = pkbf(h[0], h[1]); hi4.y = pkbf(h[2], h[3]);
    hi4.z = pkbf(h[4], h[5]); hi4.w = pkbf(h[6], h[7]);
    lo4.x = pkbf(v[0] - h[0], v[1] - h[1]);
    lo4.y = pkbf(v[2] - h[2], v[3] - h[3]);
    lo4.z = pkbf(v[4] - h[4], v[5] - h[5]);
    lo4.w = pkbf(v[6] - h[6], v[7] - h[7]);
    uint32_t off = (uint32_t)pass * 32768 + soff(n, ch * 16);
    *(uint4*)((char*)whi + off) = hi4;
    *(uint4*)((char*)wlo + off) = lo4;
}

// ===========================================================================
// mma.sync helpers
// ===========================================================================
__device__ __forceinline__ uint32_t smem_u32(const void* p) {
    uint32_t a;
    asm("{ .reg .u64 t; cvta.to.shared.u64 t, %1; cvt.u32.u64 %0, t; }"
        : "=r"(a) : "l"(p));
    return a;
}

__device__ __forceinline__ void ldsm4(uint32_t& r0, uint32_t& r1,
                                      uint32_t& r2, uint32_t& r3, uint32_t addr) {
    asm volatile("ldmatrix.sync.aligned.m8n8.x4.shared.b16 {%0,%1,%2,%3}, [%4];"
                 : "=r"(r0), "=r"(r1), "=r"(r2), "=r"(r3) : "r"(addr));
}

__device__ __forceinline__ void mma16816(float* c, uint32_t a0, uint32_t a1,
                                         uint32_t a2, uint32_t a3,
                                         uint32_t b0, uint32_t b1) {
    asm volatile(
        "mma.sync.aligned.m16n8k16.row.col.f32.bf16.bf16.f32 "
        "{%0,%1,%2,%3}, {%4,%5,%6,%7}, {%8,%9}, {%0,%1,%2,%3};"
        : "+f"(c[0]), "+f"(c[1]), "+f"(c[2]), "+f"(c[3])
        : "r"(a0), "r"(a1), "r"(a2), "r"(a3), "r"(b0), "r"(b1));
}

// ===========================================================================
// Fused SAGE layer GEMM (mma.sync bf16 3-term split) + fused BN stats.
// Out = X @ Ws + Agg @ Wn + bias; X/Agg supplied pre-split as bf16 hi/lo.
// ===========================================================================
__global__ __launch_bounds__(512, 1) void sage_mma_kernel(
    const uint4* __restrict__ xhi4, const uint4* __restrict__ xlo4,
    const uint4* __restrict__ ahi4, const uint4* __restrict__ alo4,
    const uint4* __restrict__ wthi, const uint4* __restrict__ wtlo,
    const float* __restrict__ bias,
    float2* __restrict__ Out2,
    float* __restrict__ stats, int withBN)
{
    extern __shared__ char smem[];
    const uint32_t sbase = smem_u32(smem);
    const int tid = threadIdx.x;
    const int w = tid >> 5;
    const int lane = tid & 31;
    const int row0 = blockIdx.x * TILE_M;
    const int m0 = (w & 7) * 16;
    const int nhalf = w >> 3;

    float* s_sum = (float*)(smem + SM_STATS);
    float* s_sq = s_sum + 128;
    if (withBN && tid < 256) s_sum[tid] = 0.f;

    float acc[8][4];
#pragma unroll
    for (int nt = 0; nt < 8; ++nt)
#pragma unroll
        for (int q = 0; q < 4; ++q) acc[nt][q] = 0.f;

    const int aRow = m0 + (lane & 15);
    const uint32_t aBase = sbase + SM_XHI + (uint32_t)aRow * 256;
    const uint32_t aXor = (uint32_t)(aRow & 7) << 4;
    const uint32_t aSel = ((lane >> 4) & 1) * 16;

    uint32_t bBase[4], bXor[4];
#pragma unroll
    for (int ntp = 0; ntp < 4; ++ntp) {
        int bRow = nhalf * 64 + ntp * 16 + ((lane >> 4) & 1) * 8 + (lane & 7);
        bBase[ntp] = sbase + SM_WHI + (uint32_t)bRow * 256;
        bXor[ntp] = (uint32_t)(bRow & 7) << 4;
    }
    const uint32_t bSel = ((lane >> 3) & 1) * 16;

#pragma unroll
    for (int pass = 0; pass < 2; ++pass) {
        const uint4* Hi4 = (pass == 0) ? xhi4 : ahi4;
        const uint4* Lo4 = (pass == 0) ? xlo4 : alo4;

        __syncthreads();  // protect SMEM from previous pass readers

        // ---- Fill X/Agg tile: pure bf16 copies with swizzle
#pragma unroll
        for (int it = 0; it < 4; ++it) {
            int idx = tid + it * 512;     // 0..2047
            int m = idx >> 4;
            int ch = idx & 15;
            int gr = row0 + m;
            uint4 hv = make_uint4(0, 0, 0, 0), lv = make_uint4(0, 0, 0, 0);
            if (gr < N_NODES) {
                hv = __ldg(&Hi4[gr * 16 + ch]);
                lv = __ldg(&Lo4[gr * 16 + ch]);
            }
            uint32_t off = soff(m, ch * 16);
            *(uint4*)(smem + SM_XHI + off) = hv;
            *(uint4*)(smem + SM_XLO + off) = lv;
        }

        // ---- Copy W image (hi/lo, 32KB each) for this pass
        {
            const uint4* srcH = wthi + pass * 2048;
            const uint4* srcL = wtlo + pass * 2048;
#pragma unroll
            for (int it = 0; it < 4; ++it) {
                int idx = tid + it * 512;
                ((uint4*)(smem + SM_WHI))[idx] = __ldg(&srcH[idx]);
                ((uint4*)(smem + SM_WLO))[idx] = __ldg(&srcL[idx]);
            }
        }
        __syncthreads();

        // ---- MMA main loop
#pragma unroll
        for (int ks = 0; ks < 8; ++ks) {
            uint32_t aoff = ((uint32_t)(ks * 32) + aSel) ^ aXor;
            uint32_t ah0, ah1, ah2, ah3, al0, al1, al2, al3;
            ldsm4(ah0, ah1, ah2, ah3, aBase + aoff);
            ldsm4(al0, al1, al2, al3, aBase + 32768 + aoff);
#pragma unroll
            for (int ntp = 0; ntp < 4; ++ntp) {
                uint32_t boff = ((uint32_t)(ks * 32) + bSel) ^ bXor[ntp];
                uint32_t bh0, bh1, bh2, bh3, bl0, bl1, bl2, bl3;
                ldsm4(bh0, bh1, bh2, bh3, bBase[ntp] + boff);
                ldsm4(bl0, bl1, bl2, bl3, bBase[ntp] + 32768 + boff);
                mma16816(acc[2 * ntp], ah0, ah1, ah2, ah3, bh0, bh1);
                mma16816(acc[2 * ntp], ah0, ah1, ah2, ah3, bl0, bl1);
                mma16816(acc[2 * ntp], al0, al1, al2, al3, bh0, bh1);
                mma16816(acc[2 * ntp + 1], ah0, ah1, ah2, ah3, bh2, bh3);
                mma16816(acc[2 * ntp + 1], ah0, ah1, ah2, ah3, bl2, bl3);
                mma16816(acc[2 * ntp + 1], al0, al1, al2, al3, bh2, bh3);
            }
        }
    }

    // ---- Epilogue: bias + store + fused BN stats
    {
        int g = lane >> 2;
        int i = lane & 3;
        int grA = row0 + m0 + g;
        int grB = grA + 8;
        bool vA = grA < N_NODES, vB = grB < N_NODES;
#pragma unroll
        for (int nt = 0; nt < 8; ++nt) {
            int col = nhalf * 64 + nt * 8 + 2 * i;
            float2 bv = __ldg(&((const float2*)bias)[col >> 1]);
            float hA0 = acc[nt][0] + bv.x, hA1 = acc[nt][1] + bv.y;
            float hB0 = acc[nt][2] + bv.x, hB1 = acc[nt][3] + bv.y;
            if (vA) Out2[(size_t)grA * 64 + (col >> 1)] = make_float2(hA0, hA1);
            if (vB) Out2[(size_t)grB * 64 + (col >> 1)] = make_float2(hB0, hB1);
            if (withBN) {
                float s0 = (vA ? hA0 : 0.f) + (vB ? hB0 : 0.f);
                float s1 = (vA ? hA1 : 0.f) + (vB ? hB1 : 0.f);
                float q0 = (vA ? hA0 * hA0 : 0.f) + (vB ? hB0 * hB0 : 0.f);
                float q1 = (vA ? hA1 * hA1 : 0.f) + (vB ? hB1 * hB1 : 0.f);
#pragma unroll
                for (int off = 16; off >= 4; off >>= 1) {
                    s0 += __shfl_down_sync(~0u, s0, off);
                    s1 += __shfl_down_sync(~0u, s1, off);
                    q0 += __shfl_down_sync(~0u, q0, off);
                    q1 += __shfl_down_sync(~0u, q1, off);
                }
                if (lane < 4) {
                    atomicAdd(&s_sum[col], s0);
                    atomicAdd(&s_sum[col + 1], s1);
                    atomicAdd(&s_sq[col], q0);
                    atomicAdd(&s_sq[col + 1], q1);
                }
            }
        }
    }
    if (withBN) {
        __syncthreads();
        if (tid < 128) {
            atomicAdd(&stats[tid], s_sum[tid]);
            atomicAdd(&stats[128 + tid], s_sq[tid]);
        }
    }
}

// ===========================================================================
__global__ void bn_finalize_kernel(float* __restrict__ stats,
                                   const float* __restrict__ gamma,
                                   const float* __restrict__ beta,
                                   float* __restrict__ affine) {
    int j = threadIdx.x;  // 128 threads
    const float invN = 1.0f / (float)N_NODES;
    float mu = stats[j] * invN;
    float var = stats[128 + j] * invN - mu * mu;
    float s = gamma[j] * rsqrtf(var + EPS);
    affine[j] = s;
    affine[128 + j] = beta[j] - mu * s;
    stats[j] = 0.f;
    stats[128 + j] = 0.f;
}

// ===========================================================================
extern "C" void kernel_launch(void* const* d_in, const int* in_sizes, int n_in,
                              void* d_out, int out_size) {
    const float* x   = (const float*)d_in[0];
    const int*   src = (const int*)  d_in[1];
    const int*   dst = (const int*)  d_in[2];
    const float* Ws1 = (const float*)d_in[3];
    const float* Wn1 = (const float*)d_in[4];
    const float* b1  = (const float*)d_in[5];
    const float* ga1 = (const float*)d_in[6];
    const float* be1 = (const float*)d_in[7];
    const float* Ws2 = (const float*)d_in[8];
    const float* Wn2 = (const float*)d_in[9];
    const float* b2  = (const float*)d_in[10];
    const float* ga2 = (const float*)d_in[11];
    const float* be2 = (const float*)d_in[12];
    const float* Ws3 = (const float*)d_in[13];
    const float* Wn3 = (const float*)d_in[14];
    const float* b3  = (const float*)d_in[15];
    float* out = (float*)d_out;

    float *bufA, *bufB, *invdeg, *stats, *aff1, *aff2;
    int *rowptr, *cursor, *csrsrc;
    uint4 *xhi, *xlo, *agghi, *agglo, *wthi, *wtlo;
    cudaGetSymbolAddress((void**)&bufA,   g_bufA);
    cudaGetSymbolAddress((void**)&bufB,   g_bufB);
    cudaGetSymbolAddress((void**)&xhi,    g_xhi);
    cudaGetSymbolAddress((void**)&xlo,    g_xlo);
    cudaGetSymbolAddress((void**)&agghi,  g_agghi);
    cudaGetSymbolAddress((void**)&agglo,  g_agglo);
    cudaGetSymbolAddress((void**)&rowptr, g_rowptr);
    cudaGetSymbolAddress((void**)&cursor, g_cursor);
    cudaGetSymbolAddress((void**)&csrsrc, g_csrsrc);
    cudaGetSymbolAddress((void**)&invdeg, g_invdeg);
    cudaGetSymbolAddress((void**)&stats,  g_stats);
    cudaGetSymbolAddress((void**)&aff1,   g_affine1);
    cudaGetSymbolAddress((void**)&aff2,   g_affine2);
    cudaGetSymbolAddress((void**)&wthi,   g_wthi);
    cudaGetSymbolAddress((void**)&wtlo,   g_wtlo);

    cudaFuncSetAttribute(sage_mma_kernel,
                         cudaFuncAttributeMaxDynamicSharedMemorySize, SM_TOTAL);

    const int gthr_blocks = (N_NODES * 32 + 255) / 256;
    const int prep_blocks = (N_NODES * 32 + 255) / 256;

    // Build CSR (scan also zeroes stats).
    zero_int_kernel<<<(N_NODES / 4 + 255) / 256, 256>>>((int4*)cursor, N_NODES / 4);
    hist_kernel<<<(N_EDGES + 255) / 256, 256>>>(dst, cursor);
    scan_kernel<<<1, 1024>>>(cursor, rowptr, cursor, invdeg, stats);
    fill_kernel<<<(N_EDGES + 255) / 256, 256>>>(src, dst, cursor, csrsrc);

    // Layer 1
    wprep_kernel<<<16, 256>>>(Ws1, Wn1, wthi, wtlo);
    prep_kernel<<<prep_blocks, 256>>>((const float4*)x, nullptr, 0,
                                      (uint2*)xhi, (uint2*)xlo);
    gather_kernel<<<gthr_blocks, 256>>>((const uint2*)xhi, rowptr, csrsrc, invdeg,
                                        (uint2*)agghi, (uint2*)agglo);
    sage_mma_kernel<<<GEMM_BLOCKS, 512, SM_TOTAL>>>(
        xhi, xlo, agghi, agglo, wthi, wtlo, b1, (float2*)bufA, stats, 1);
    bn_finalize_kernel<<<1, 128>>>(stats, ga1, be1, aff1);

    // Layer 2
    wprep_kernel<<<16, 256>>>(Ws2, Wn2, wthi, wtlo);
    prep_kernel<<<prep_blocks, 256>>>((const float4*)bufA, aff1, 1,
                                      (uint2*)xhi, (uint2*)xlo);
    gather_kernel<<<gthr_blocks, 256>>>((const uint2*)xhi, rowptr, csrsrc, invdeg,
                                        (uint2*)agghi, (uint2*)agglo);
    sage_mma_kernel<<<GEMM_BLOCKS, 512, SM_TOTAL>>>(
        xhi, xlo, agghi, agglo, wthi, wtlo, b2, (float2*)bufB, stats, 1);
    bn_finalize_kernel<<<1, 128>>>(stats, ga2, be2, aff2);

    // Layer 3
    wprep_kernel<<<16, 256>>>(Ws3, Wn3, wthi, wtlo);
    prep_kernel<<<prep_blocks, 256>>>((const float4*)bufB, aff2, 1,
                                      (uint2*)xhi, (uint2*)xlo);
    gather_kernel<<<gthr_blocks, 256>>>((const uint2*)xhi, rowptr, csrsrc, invdeg,
                                        (uint2*)agghi, (uint2*)agglo);
    sage_mma_kernel<<<GEMM_BLOCKS, 512, SM_TOTAL>>>(
        xhi, xlo, agghi, agglo, wthi, wtlo, b3, (float2*)out, stats, 0);
}

// round 8
// speedup vs baseline: 2.4992x; 1.0012x over previous
#include <cuda_runtime.h>
#include <cuda_bf16.h>
#include <cuda_fp16.h>
#include <cstdint>
#include <cstring>

#define N_NODES 50000
#define N_EDGES 800000
#define EPS 1e-5f

#define TILE_M 128
#define GEMM_BLOCKS ((N_NODES + TILE_M - 1) / TILE_M)
#define PREP_BLOCKS ((N_NODES * 32 + 255) / 256)

// SMEM layout (bytes)
#define SM_XHI 0
#define SM_XLO 32768
#define SM_WHI 65536
#define SM_WLO 98304
#define SM_STATS 131072
#define SM_TOTAL (131072 + 1024)

// Scratch (__device__ globals, allocation-free rule)
// split-bf16 row = 128 bf16 = 256 B = 16 uint4 per node; fp16 row likewise.
__device__ float g_bufA[N_NODES * 128];
__device__ float g_bufB[N_NODES * 128];
__device__ uint4 g_xhi[N_NODES * 16];   // bf16 hi activations (for GEMM)
__device__ uint4 g_xlo[N_NODES * 16];   // bf16 lo activations (for GEMM)
__device__ uint4 g_xh16[N_NODES * 16];  // fp16 activations (for gather)
__device__ uint4 g_agghi[N_NODES * 16]; // split bf16 aggregates
__device__ uint4 g_agglo[N_NODES * 16];
__device__ int   g_rowptr[N_NODES + 1];
__device__ int   g_cursor[N_NODES];
__device__ int   g_csrsrc[N_EDGES];
__device__ float g_invdeg[N_NODES];
__device__ float g_stats[256];
__device__ float g_affine1[256];
__device__ float g_affine2[256];
__device__ uint4 g_wthi[2 * 2048];
__device__ uint4 g_wtlo[2 * 2048];

// ===========================================================================
// CSR build
// ===========================================================================
__global__ void zero_int_kernel(int4* __restrict__ p, int n4) {
    int i = blockIdx.x * blockDim.x + threadIdx.x;
    if (i < n4) p[i] = make_int4(0, 0, 0, 0);
}

__global__ void hist_kernel(const int2* __restrict__ dst2, int* __restrict__ cnt) {
    int e = blockIdx.x * blockDim.x + threadIdx.x;
    if (e < N_EDGES / 2) {
        int2 d = __ldg(&dst2[e]);
        atomicAdd(&cnt[d.x], 1);
        atomicAdd(&cnt[d.y], 1);
    }
}

__global__ __launch_bounds__(1024) void scan_kernel(
    const int* __restrict__ cnt_in, int* __restrict__ rowptr,
    int* __restrict__ cursor, float* __restrict__ invdeg,
    float* __restrict__ stats)
{
    __shared__ int wsum[32];
    __shared__ int s_carry;
    const int t = threadIdx.x, lane = t & 31, w = t >> 5;
    if (t == 0) s_carry = 0;
    if (t < 256) stats[t] = 0.f;
    __syncthreads();

    const int CHUNK = 4096;
    for (int base = 0; base < N_NODES; base += CHUNK) {
        int i0 = base + t * 4;
        int v[4];
#pragma unroll
        for (int j = 0; j < 4; ++j)
            v[j] = (i0 + j < N_NODES) ? cnt_in[i0 + j] : 0;
        int tsum = v[0] + v[1] + v[2] + v[3];

        int x = tsum;
#pragma unroll
        for (int o = 1; o < 32; o <<= 1) {
            int y = __shfl_up_sync(~0u, x, o);
            if (lane >= o) x += y;
        }
        if (lane == 31) wsum[w] = x;
        __syncthreads();
        if (w == 0) {
            int s = wsum[lane];
#pragma unroll
            for (int o = 1; o < 32; o <<= 1) {
                int y = __shfl_up_sync(~0u, s, o);
                if (lane >= o) s += y;
            }
            wsum[lane] = s;
        }
        __syncthreads();
        int woff = (w == 0) ? 0 : wsum[w - 1];
        int run = s_carry + woff + (x - tsum);
#pragma unroll
        for (int j = 0; j < 4; ++j) {
            int i = i0 + j;
            if (i < N_NODES) {
                rowptr[i] = run;
                cursor[i] = run;
                invdeg[i] = 1.0f / fmaxf((float)v[j], 1.0f);
            }
            run += v[j];
        }
        __syncthreads();
        if (t == 1023) s_carry += wsum[31];
        __syncthreads();
    }
    if (t == 0) rowptr[N_NODES] = s_carry;
}

__global__ void fill_kernel(const int2* __restrict__ src2, const int2* __restrict__ dst2,
                            int* __restrict__ cursor, int* __restrict__ csrsrc) {
    int e = blockIdx.x * blockDim.x + threadIdx.x;
    if (e < N_EDGES / 2) {
        int2 s = __ldg(&src2[e]);
        int2 d = __ldg(&dst2[e]);
        int p0 = atomicAdd(&cursor[d.x], 1);
        int p1 = atomicAdd(&cursor[d.y], 1);
        csrsrc[p0] = s.x;
        csrsrc[p1] = s.y;
    }
}

// ===========================================================================
// bf16/fp16 helpers
// ===========================================================================
__device__ __forceinline__ uint32_t pkbf(float a, float b) {
    __nv_bfloat162 h = __float22bfloat162_rn(make_float2(a, b));
    uint32_t r;
    memcpy(&r, &h, 4);
    return r;
}
__device__ __forceinline__ uint32_t pkhf(float a, float b) {
    __half2 h = __float22half2_rn(make_float2(a, b));
    uint32_t r;
    memcpy(&r, &h, 4);
    return r;
}
__device__ __forceinline__ float bfhi(float a) {
    return __bfloat162float(__float2bfloat16_rn(a));
}
__device__ __forceinline__ float2 hf2f(uint32_t u) {
    __half2 h;
    memcpy(&h, &u, 4);
    return __half22float2(h);
}
__device__ __forceinline__ float4 bn_relu4(float4 v, float4 sc, float4 sh) {
    v.x = fmaxf(fmaf(v.x, sc.x, sh.x), 0.f);
    v.y = fmaxf(fmaf(v.y, sc.y, sh.y), 0.f);
    v.z = fmaxf(fmaf(v.z, sc.z, sh.z), 0.f);
    v.w = fmaxf(fmaf(v.w, sc.w, sh.w), 0.f);
    return v;
}

// Swizzled byte offset within a 128-row x 256B tile.
__device__ __forceinline__ uint32_t soff(int r, int byte) {
    return (uint32_t)(r * 256 + (byte ^ ((r & 7) << 4)));
}

// ===========================================================================
// prep (+wprep folded in): blocks [0, PREP_BLOCKS) process activations;
// the 16 extra blocks build the swizzled W^T hi/lo images.
// ===========================================================================
__global__ __launch_bounds__(256) void prep_kernel(
    const float4* __restrict__ H,
    const float* __restrict__ affine, int useAffine,
    uint2* __restrict__ xhi, uint2* __restrict__ xlo, uint2* __restrict__ xh16,
    const float* __restrict__ Ws, const float* __restrict__ Wn,
    uint4* __restrict__ whi, uint4* __restrict__ wlo)
{
    if (blockIdx.x >= PREP_BLOCKS) {
        // ---- W prep: 16 blocks x 256 threads = 4096 work items
        int idx = (blockIdx.x - PREP_BLOCKS) * 256 + threadIdx.x;
        int pass = idx >> 11;
        int n = (idx >> 4) & 127;
        int ch = idx & 15;
        const float* W = pass ? Wn : Ws;
        float v[8], h[8];
#pragma unroll
        for (int j = 0; j < 8; ++j) {
            v[j] = __ldg(&W[(ch * 8 + j) * 128 + n]);
            h[j] = bfhi(v[j]);
        }
        uint4 hi4, lo4;
        hi4.x = pkbf(h[0], h[1]); hi4.y = pkbf(h[2], h[3]);
        hi4.z = pkbf(h[4], h[5]); hi4.w = pkbf(h[6], h[7]);
        lo4.x = pkbf(v[0] - h[0], v[1] - h[1]);
        lo4.y = pkbf(v[2] - h[2], v[3] - h[3]);
        lo4.z = pkbf(v[4] - h[4], v[5] - h[5]);
        lo4.w = pkbf(v[6] - h[6], v[7] - h[7]);
        uint32_t off = (uint32_t)pass * 32768 + soff(n, ch * 16);
        *(uint4*)((char*)whi + off) = hi4;
        *(uint4*)((char*)wlo + off) = lo4;
        return;
    }
    int gid = blockIdx.x * blockDim.x + threadIdx.x;
    if (gid >= N_NODES * 32) return;
    float4 v = H[gid];
    if (useAffine) {
        int c = gid & 31;
        float4 sc = __ldg(&((const float4*)affine)[c]);
        float4 sh = __ldg(&((const float4*)affine)[32 + c]);
        v = bn_relu4(v, sc, sh);
    }
    float h0 = bfhi(v.x), h1 = bfhi(v.y), h2 = bfhi(v.z), h3 = bfhi(v.w);
    xhi[gid] = make_uint2(pkbf(h0, h1), pkbf(h2, h3));
    xlo[gid] = make_uint2(pkbf(v.x - h0, v.y - h1), pkbf(v.z - h2, v.w - h3));
    xh16[gid] = make_uint2(pkhf(v.x, v.y), pkhf(v.z, v.w));
}

// ===========================================================================
// Gather (warp per node, fp16 inputs, fp32 accumulate, split-bf16 output)
// ===========================================================================
__global__ __launch_bounds__(256) void gather_kernel(
    const uint2* __restrict__ xh16,
    const int* __restrict__ rowptr,
    const int* __restrict__ csrsrc,
    const float* __restrict__ invdeg,
    uint2* __restrict__ agghi, uint2* __restrict__ agglo)
{
    int gid = blockIdx.x * blockDim.x + threadIdx.x;
    int node = gid >> 5;
    if (node >= N_NODES) return;
    int lane = gid & 31;

    int beg = __ldg(&rowptr[node]);
    int end = __ldg(&rowptr[node + 1]);
    float inv = __ldg(&invdeg[node]);

    float a0 = 0.f, a1 = 0.f, a2 = 0.f, a3 = 0.f;
    int p = beg;
    for (; p + 7 < end; p += 8) {
        uint2 d[8];
#pragma unroll
        for (int j = 0; j < 8; ++j) {
            int nb = __ldg(&csrsrc[p + j]);
            d[j] = __ldg(&xh16[nb * 32 + lane]);
        }
#pragma unroll
        for (int j = 0; j < 8; ++j) {
            float2 f0 = hf2f(d[j].x), f1 = hf2f(d[j].y);
            a0 += f0.x; a1 += f0.y; a2 += f1.x; a3 += f1.y;
        }
    }
    for (; p + 3 < end; p += 4) {
        uint2 d[4];
#pragma unroll
        for (int j = 0; j < 4; ++j) {
            int nb = __ldg(&csrsrc[p + j]);
            d[j] = __ldg(&xh16[nb * 32 + lane]);
        }
#pragma unroll
        for (int j = 0; j < 4; ++j) {
            float2 f0 = hf2f(d[j].x), f1 = hf2f(d[j].y);
            a0 += f0.x; a1 += f0.y; a2 += f1.x; a3 += f1.y;
        }
    }
    for (; p < end; ++p) {
        int nb = __ldg(&csrsrc[p]);
        uint2 d = __ldg(&xh16[nb * 32 + lane]);
        float2 f0 = hf2f(d.x), f1 = hf2f(d.y);
        a0 += f0.x; a1 += f0.y; a2 += f1.x; a3 += f1.y;
    }
    a0 *= inv; a1 *= inv; a2 *= inv; a3 *= inv;
    float h0 = bfhi(a0), h1 = bfhi(a1), h2 = bfhi(a2), h3 = bfhi(a3);
    agghi[node * 32 + lane] = make_uint2(pkbf(h0, h1), pkbf(h2, h3));
    agglo[node * 32 + lane] = make_uint2(pkbf(a0 - h0, a1 - h1), pkbf(a2 - h2, a3 - h3));
}

// ===========================================================================
// mma.sync helpers
// ===========================================================================
__device__ __forceinline__ uint32_t smem_u32(const void* p) {
    uint32_t a;
    asm("{ .reg .u64 t; cvta.to.shared.u64 t, %1; cvt.u32.u64 %0, t; }"
        : "=r"(a) : "l"(p));
    return a;
}

__device__ __forceinline__ void ldsm4(uint32_t& r0, uint32_t& r1,
                                      uint32_t& r2, uint32_t& r3, uint32_t addr) {
    asm volatile("ldmatrix.sync.aligned.m8n8.x4.shared.b16 {%0,%1,%2,%3}, [%4];"
                 : "=r"(r0), "=r"(r1), "=r"(r2), "=r"(r3) : "r"(addr));
}

__device__ __forceinline__ void mma16816(float* c, uint32_t a0, uint32_t a1,
                                         uint32_t a2, uint32_t a3,
                                         uint32_t b0, uint32_t b1) {
    asm volatile(
        "mma.sync.aligned.m16n8k16.row.col.f32.bf16.bf16.f32 "
        "{%0,%1,%2,%3}, {%4,%5,%6,%7}, {%8,%9}, {%0,%1,%2,%3};"
        : "+f"(c[0]), "+f"(c[1]), "+f"(c[2]), "+f"(c[3])
        : "r"(a0), "r"(a1), "r"(a2), "r"(a3), "r"(b0), "r"(b1));
}

// ===========================================================================
// Fused SAGE layer GEMM (mma.sync bf16 3-term split) + fused BN stats.
// ===========================================================================
__global__ __launch_bounds__(512, 1) void sage_mma_kernel(
    const uint4* __restrict__ xhi4, const uint4* __restrict__ xlo4,
    const uint4* __restrict__ ahi4, const uint4* __restrict__ alo4,
    const uint4* __restrict__ wthi, const uint4* __restrict__ wtlo,
    const float* __restrict__ bias,
    float2* __restrict__ Out2,
    float* __restrict__ stats, int withBN)
{
    extern __shared__ char smem[];
    const uint32_t sbase = smem_u32(smem);
    const int tid = threadIdx.x;
    const int w = tid >> 5;
    const int lane = tid & 31;
    const int row0 = blockIdx.x * TILE_M;
    const int m0 = (w & 7) * 16;
    const int nhalf = w >> 3;

    float* s_sum = (float*)(smem + SM_STATS);
    float* s_sq = s_sum + 128;
    if (withBN && tid < 256) s_sum[tid] = 0.f;

    float acc[8][4];
#pragma unroll
    for (int nt = 0; nt < 8; ++nt)
#pragma unroll
        for (int q = 0; q < 4; ++q) acc[nt][q] = 0.f;

    const int aRow = m0 + (lane & 15);
    const uint32_t aBase = sbase + SM_XHI + (uint32_t)aRow * 256;
    const uint32_t aXor = (uint32_t)(aRow & 7) << 4;
    const uint32_t aSel = ((lane >> 4) & 1) * 16;

    uint32_t bBase[4], bXor[4];
#pragma unroll
    for (int ntp = 0; ntp < 4; ++ntp) {
        int bRow = nhalf * 64 + ntp * 16 + ((lane >> 4) & 1) * 8 + (lane & 7);
        bBase[ntp] = sbase + SM_WHI + (uint32_t)bRow * 256;
        bXor[ntp] = (uint32_t)(bRow & 7) << 4;
    }
    const uint32_t bSel = ((lane >> 3) & 1) * 16;

#pragma unroll
    for (int pass = 0; pass < 2; ++pass) {
        const uint4* Hi4 = (pass == 0) ? xhi4 : ahi4;
        const uint4* Lo4 = (pass == 0) ? xlo4 : alo4;

        __syncthreads();

        // ---- Fill X/Agg tile: pure bf16 copies with swizzle
#pragma unroll
        for (int it = 0; it < 4; ++it) {
            int idx = tid + it * 512;     // 0..2047
            int m = idx >> 4;
            int ch = idx & 15;
            int gr = row0 + m;
            uint4 hv = make_uint4(0, 0, 0, 0), lv = make_uint4(0, 0, 0, 0);
            if (gr < N_NODES) {
                hv = __ldg(&Hi4[gr * 16 + ch]);
                lv = __ldg(&Lo4[gr * 16 + ch]);
            }
            uint32_t off = soff(m, ch * 16);
            *(uint4*)(smem + SM_XHI + off) = hv;
            *(uint4*)(smem + SM_XLO + off) = lv;
        }

        // ---- Copy W image (hi/lo, 32KB each) for this pass
        {
            const uint4* srcH = wthi + pass * 2048;
            const uint4* srcL = wtlo + pass * 2048;
#pragma unroll
            for (int it = 0; it < 4; ++it) {
                int idx = tid + it * 512;
                ((uint4*)(smem + SM_WHI))[idx] = __ldg(&srcH[idx]);
                ((uint4*)(smem + SM_WLO))[idx] = __ldg(&srcL[idx]);
            }
        }
        __syncthreads();

        // ---- MMA main loop
#pragma unroll
        for (int ks = 0; ks < 8; ++ks) {
            uint32_t aoff = ((uint32_t)(ks * 32) + aSel) ^ aXor;
            uint32_t ah0, ah1, ah2, ah3, al0, al1, al2, al3;
            ldsm4(ah0, ah1, ah2, ah3, aBase + aoff);
            ldsm4(al0, al1, al2, al3, aBase + 32768 + aoff);
#pragma unroll
            for (int ntp = 0; ntp < 4; ++ntp) {
                uint32_t boff = ((uint32_t)(ks * 32) + bSel) ^ bXor[ntp];
                uint32_t bh0, bh1, bh2, bh3, bl0, bl1, bl2, bl3;
                ldsm4(bh0, bh1, bh2, bh3, bBase[ntp] + boff);
                ldsm4(bl0, bl1, bl2, bl3, bBase[ntp] + 32768 + boff);
                mma16816(acc[2 * ntp], ah0, ah1, ah2, ah3, bh0, bh1);
                mma16816(acc[2 * ntp], ah0, ah1, ah2, ah3, bl0, bl1);
                mma16816(acc[2 * ntp], al0, al1, al2, al3, bh0, bh1);
                mma16816(acc[2 * ntp + 1], ah0, ah1, ah2, ah3, bh2, bh3);
                mma16816(acc[2 * ntp + 1], ah0, ah1, ah2, ah3, bl2, bl3);
                mma16816(acc[2 * ntp + 1], al0, al1, al2, al3, bh2, bh3);
            }
        }
    }

    // ---- Epilogue: bias + store + fused BN stats
    {
        int g = lane >> 2;
        int i = lane & 3;
        int grA = row0 + m0 + g;
        int grB = grA + 8;
        bool vA = grA < N_NODES, vB = grB < N_NODES;
#pragma unroll
        for (int nt = 0; nt < 8; ++nt) {
            int col = nhalf * 64 + nt * 8 + 2 * i;
            float2 bv = __ldg(&((const float2*)bias)[col >> 1]);
            float hA0 = acc[nt][0] + bv.x, hA1 = acc[nt][1] + bv.y;
            float hB0 = acc[nt][2] + bv.x, hB1 = acc[nt][3] + bv.y;
            if (vA) Out2[(size_t)grA * 64 + (col >> 1)] = make_float2(hA0, hA1);
            if (vB) Out2[(size_t)grB * 64 + (col >> 1)] = make_float2(hB0, hB1);
            if (withBN) {
                float s0 = (vA ? hA0 : 0.f) + (vB ? hB0 : 0.f);
                float s1 = (vA ? hA1 : 0.f) + (vB ? hB1 : 0.f);
                float q0 = (vA ? hA0 * hA0 : 0.f) + (vB ? hB0 * hB0 : 0.f);
                float q1 = (vA ? hA1 * hA1 : 0.f) + (vB ? hB1 * hB1 : 0.f);
#pragma unroll
                for (int off = 16; off >= 4; off >>= 1) {
                    s0 += __shfl_down_sync(~0u, s0, off);
                    s1 += __shfl_down_sync(~0u, s1, off);
                    q0 += __shfl_down_sync(~0u, q0, off);
                    q1 += __shfl_down_sync(~0u, q1, off);
                }
                if (lane < 4) {
                    atomicAdd(&s_sum[col], s0);
                    atomicAdd(&s_sum[col + 1], s1);
                    atomicAdd(&s_sq[col], q0);
                    atomicAdd(&s_sq[col + 1], q1);
                }
            }
        }
    }
    if (withBN) {
        __syncthreads();
        if (tid < 128) {
            atomicAdd(&stats[tid], s_sum[tid]);
            atomicAdd(&stats[128 + tid], s_sq[tid]);
        }
    }
}

// ===========================================================================
__global__ void bn_finalize_kernel(float* __restrict__ stats,
                                   const float* __restrict__ gamma,
                                   const float* __restrict__ beta,
                                   float* __restrict__ affine) {
    int j = threadIdx.x;  // 128 threads
    const float invN = 1.0f / (float)N_NODES;
    float mu = stats[j] * invN;
    float var = stats[128 + j] * invN - mu * mu;
    float s = gamma[j] * rsqrtf(var + EPS);
    affine[j] = s;
    affine[128 + j] = beta[j] - mu * s;
    stats[j] = 0.f;
    stats[128 + j] = 0.f;
}

// ===========================================================================
extern "C" void kernel_launch(void* const* d_in, const int* in_sizes, int n_in,
                              void* d_out, int out_size) {
    const float* x   = (const float*)d_in[0];
    const int*   src = (const int*)  d_in[1];
    const int*   dst = (const int*)  d_in[2];
    const float* Ws1 = (const float*)d_in[3];
    const float* Wn1 = (const float*)d_in[4];
    const float* b1  = (const float*)d_in[5];
    const float* ga1 = (const float*)d_in[6];
    const float* be1 = (const float*)d_in[7];
    const float* Ws2 = (const float*)d_in[8];
    const float* Wn2 = (const float*)d_in[9];
    const float* b2  = (const float*)d_in[10];
    const float* ga2 = (const float*)d_in[11];
    const float* be2 = (const float*)d_in[12];
    const float* Ws3 = (const float*)d_in[13];
    const float* Wn3 = (const float*)d_in[14];
    const float* b3  = (const float*)d_in[15];
    float* out = (float*)d_out;

    float *bufA, *bufB, *invdeg, *stats, *aff1, *aff2;
    int *rowptr, *cursor, *csrsrc;
    uint4 *xhi, *xlo, *xh16, *agghi, *agglo, *wthi, *wtlo;
    cudaGetSymbolAddress((void**)&bufA,   g_bufA);
    cudaGetSymbolAddress((void**)&bufB,   g_bufB);
    cudaGetSymbolAddress((void**)&xhi,    g_xhi);
    cudaGetSymbolAddress((void**)&xlo,    g_xlo);
    cudaGetSymbolAddress((void**)&xh16,   g_xh16);
    cudaGetSymbolAddress((void**)&agghi,  g_agghi);
    cudaGetSymbolAddress((void**)&agglo,  g_agglo);
    cudaGetSymbolAddress((void**)&rowptr, g_rowptr);
    cudaGetSymbolAddress((void**)&cursor, g_cursor);
    cudaGetSymbolAddress((void**)&csrsrc, g_csrsrc);
    cudaGetSymbolAddress((void**)&invdeg, g_invdeg);
    cudaGetSymbolAddress((void**)&stats,  g_stats);
    cudaGetSymbolAddress((void**)&aff1,   g_affine1);
    cudaGetSymbolAddress((void**)&aff2,   g_affine2);
    cudaGetSymbolAddress((void**)&wthi,   g_wthi);
    cudaGetSymbolAddress((void**)&wtlo,   g_wtlo);

    cudaFuncSetAttribute(sage_mma_kernel,
                         cudaFuncAttributeMaxDynamicSharedMemorySize, SM_TOTAL);

    const int gthr_blocks = (N_NODES * 32 + 255) / 256;

    // Build CSR (scan also zeroes stats).
    zero_int_kernel<<<(N_NODES / 4 + 255) / 256, 256>>>((int4*)cursor, N_NODES / 4);
    hist_kernel<<<(N_EDGES / 2 + 255) / 256, 256>>>((const int2*)dst, cursor);
    scan_kernel<<<1, 1024>>>(cursor, rowptr, cursor, invdeg, stats);
    fill_kernel<<<(N_EDGES / 2 + 255) / 256, 256>>>((const int2*)src, (const int2*)dst,
                                                    cursor, csrsrc);

    // Layer 1
    prep_kernel<<<PREP_BLOCKS + 16, 256>>>((const float4*)x, nullptr, 0,
                                           (uint2*)xhi, (uint2*)xlo, (uint2*)xh16,
                                           Ws1, Wn1, wthi, wtlo);
    gather_kernel<<<gthr_blocks, 256>>>((const uint2*)xh16, rowptr, csrsrc, invdeg,
                                        (uint2*)agghi, (uint2*)agglo);
    sage_mma_kernel<<<GEMM_BLOCKS, 512, SM_TOTAL>>>(
        xhi, xlo, agghi, agglo, wthi, wtlo, b1, (float2*)bufA, stats, 1);
    bn_finalize_kernel<<<1, 128>>>(stats, ga1, be1, aff1);

    // Layer 2
    prep_kernel<<<PREP_BLOCKS + 16, 256>>>((const float4*)bufA, aff1, 1,
                                           (uint2*)xhi, (uint2*)xlo, (uint2*)xh16,
                                           Ws2, Wn2, wthi, wtlo);
    gather_kernel<<<gthr_blocks, 256>>>((const uint2*)xh16, rowptr, csrsrc, invdeg,
                                        (uint2*)agghi, (uint2*)agglo);
    sage_mma_kernel<<<GEMM_BLOCKS, 512, SM_TOTAL>>>(
        xhi, xlo, agghi, agglo, wthi, wtlo, b2, (float2*)bufB, stats, 1);
    bn_finalize_kernel<<<1, 128>>>(stats, ga2, be2, aff2);

    // Layer 3
    prep_kernel<<<PREP_BLOCKS + 16, 256>>>((const float4*)bufB, aff2, 1,
                                           (uint2*)xhi, (uint2*)xlo, (uint2*)xh16,
                                           Ws3, Wn3, wthi, wtlo);
    gather_kernel<<<gthr_blocks, 256>>>((const uint2*)xh16, rowptr, csrsrc, invdeg,
                                        (uint2*)agghi, (uint2*)agglo);
    sage_mma_kernel<<<GEMM_BLOCKS, 512, SM_TOTAL>>>(
        xhi, xlo, agghi, agglo, wthi, wtlo, b3, (float2*)out, stats, 0);
}